// round 3
// baseline (speedup 1.0000x reference)
#include <cuda_runtime.h>
#include <float.h>

// Problem constants (fixed shapes)
#define NNODES 50000
#define NEDGES 800000
#define FIN    128
#define HID    256

// ---------------- scratch (device globals; no allocation allowed) ----------
// NOTE: __align__(256) is load-bearing: float4 access requires 16B alignment
// and __device__ globals otherwise only get type alignment.
__device__ __align__(256) int   g_counts[NNODES];
__device__ __align__(256) int   g_rowptr[NNODES + 1];
__device__ __align__(256) int   g_wofs[NNODES];
__device__ __align__(256) int   g_ssrc[NEDGES];
__device__ __align__(256) float g_agg[(size_t)NNODES * HID];
__device__ __align__(256) float g_h1 [(size_t)NNODES * HID];
__device__ __align__(256) float g_h2 [(size_t)NNODES * HID];
__device__ __align__(256) float g_rt [(size_t)NNODES * HID];
__device__ __align__(256) float g_mv [(size_t)NNODES * HID];
__device__ int g_use32;   // 1 if edge_index is actually int32 in memory

// ---------------- dtype detection -----------------------------------------
// If the buffer really holds int64 node ids, every value is in [0, N).
// If it holds int32 pairs read as int64, values are ~v0 + v1*2^32 (huge).
__global__ void k_detect(const long long* __restrict__ ei) {
    if (threadIdx.x == 0 && blockIdx.x == 0) g_use32 = 0;
    __threadfence();
    int i = blockIdx.x * blockDim.x + threadIdx.x;
    if (i < 4096) {
        long long v = ei[i];
        if (v < 0 || v >= NNODES) atomicExch(&g_use32, 1);
    }
}

__device__ __forceinline__ int edge_at(const void* ei, size_t idx) {
    if (g_use32) return ((const int*)ei)[idx];
    return (int)((const long long*)ei)[idx];
}

// ---------------- CSR build ------------------------------------------------
__global__ void k_zero_counts() {
    int i = blockIdx.x * blockDim.x + threadIdx.x;
    if (i < NNODES) g_counts[i] = 0;
}

__global__ void k_hist(const void* __restrict__ ei) {
    int i = blockIdx.x * blockDim.x + threadIdx.x;
    if (i < NEDGES) {
        int d = edge_at(ei, (size_t)NEDGES + i);   // dst row
        if ((unsigned)d < NNODES) atomicAdd(&g_counts[d], 1);
    }
}

// single-block exclusive scan (N=50000, 1024 threads, chunked Hillis–Steele)
__global__ void k_scan() {
    __shared__ int sdata[1024];
    int tid = threadIdx.x;
    int carry = 0;
    for (int base = 0; base < NNODES; base += 1024) {
        int i = base + tid;
        int v = (i < NNODES) ? g_counts[i] : 0;
        sdata[tid] = v;
        __syncthreads();
        #pragma unroll
        for (int off = 1; off < 1024; off <<= 1) {
            int t = (tid >= off) ? sdata[tid - off] : 0;
            __syncthreads();
            sdata[tid] += t;
            __syncthreads();
        }
        if (i < NNODES) g_rowptr[i + 1] = carry + sdata[tid];
        int chunk = sdata[1023];
        __syncthreads();
        carry += chunk;
    }
    if (tid == 0) g_rowptr[0] = 0;
}

__global__ void k_copy_wofs() {
    int i = blockIdx.x * blockDim.x + threadIdx.x;
    if (i < NNODES) g_wofs[i] = g_rowptr[i];
}

__global__ void k_scatter(const void* __restrict__ ei) {
    int i = blockIdx.x * blockDim.x + threadIdx.x;
    if (i < NEDGES) {
        int s = edge_at(ei, i);
        int d = edge_at(ei, (size_t)NEDGES + i);
        if ((unsigned)d >= NNODES || (unsigned)s >= NNODES) return;
        int p = atomicAdd(&g_wofs[d], 1);
        if (p < NEDGES) g_ssrc[p] = s;
    }
}

// ---------------- segment max (one warp per node, float4 lanes) ------------
__device__ __forceinline__ float4 f4max(float4 a, float4 b) {
    return make_float4(fmaxf(a.x, b.x), fmaxf(a.y, b.y),
                       fmaxf(a.z, b.z), fmaxf(a.w, b.w));
}

template <int F>
__global__ void k_segmax(const float* __restrict__ feat, float* __restrict__ out) {
    constexpr int VPL = F / 128;  // float4 per lane (1 for F=128, 2 for F=256)
    int warp = (blockIdx.x * blockDim.x + threadIdx.x) >> 5;
    int lane = threadIdx.x & 31;
    if (warp >= NNODES) return;
    int beg = g_rowptr[warp];
    int end = g_rowptr[warp + 1];

    float4 acc[VPL];
    #pragma unroll
    for (int v = 0; v < VPL; v++)
        acc[v] = make_float4(-FLT_MAX, -FLT_MAX, -FLT_MAX, -FLT_MAX);

    int e = beg;
    for (; e + 1 < end; e += 2) {
        int s0 = g_ssrc[e], s1 = g_ssrc[e + 1];
        const float4* r0 = (const float4*)(feat + (size_t)s0 * F);
        const float4* r1 = (const float4*)(feat + (size_t)s1 * F);
        #pragma unroll
        for (int v = 0; v < VPL; v++) {
            float4 a = __ldg(&r0[v * 32 + lane]);
            float4 b = __ldg(&r1[v * 32 + lane]);
            acc[v] = f4max(acc[v], f4max(a, b));
        }
    }
    if (e < end) {
        int s0 = g_ssrc[e];
        const float4* r0 = (const float4*)(feat + (size_t)s0 * F);
        #pragma unroll
        for (int v = 0; v < VPL; v++)
            acc[v] = f4max(acc[v], __ldg(&r0[v * 32 + lane]));
    }
    if (beg == end) {
        #pragma unroll
        for (int v = 0; v < VPL; v++)
            acc[v] = make_float4(0.f, 0.f, 0.f, 0.f);
    }
    float4* orow = (float4*)(out + (size_t)warp * F);
    #pragma unroll
    for (int v = 0; v < VPL; v++)
        orow[v * 32 + lane] = acc[v];
}

// ---------------- fused SGEMM: C = relu(A@WA + B@WB + bias) ----------------
// A:[M,KA], B:[M,KB], WA:[KA,H], WB:[KB,H], C:[M,H] all row-major.
// BM=128, BN=128, BK=8, 256 threads, 8x8 per thread.
#define BM 128
#define BN 128
#define BK 8
#define TM 8
#define TN 8

__global__ __launch_bounds__(256, 2)
void k_gemm_fused(const float* __restrict__ A,  const float* __restrict__ WA, int KA,
                  const float* __restrict__ B,  const float* __restrict__ WB, int KB,
                  const float* __restrict__ bias, float* __restrict__ C,
                  int M, int Hc)
{
    __shared__ float As[BK][BM];
    __shared__ float Ws[BK][BN];

    int tid = threadIdx.x;
    int block_row = blockIdx.y * BM;
    int block_col = blockIdx.x * BN;
    int tr = tid >> 4;     // 0..15
    int tc = tid & 15;     // 0..15

    float acc[TM][TN];
    #pragma unroll
    for (int i = 0; i < TM; i++)
        #pragma unroll
        for (int j = 0; j < TN; j++) acc[i][j] = 0.f;

    const float* Aps[2] = {A, B};
    const float* Wps[2] = {WA, WB};
    int Ks[2] = {KA, KB};

    for (int ph = 0; ph < 2; ph++) {
        const float* Ap = Aps[ph];
        const float* Wp = Wps[ph];
        int K = Ks[ph];
        for (int k0 = 0; k0 < K; k0 += BK) {
            // load A tile (BM x BK), transposed into As[k][m]; one float4/thread
            int ar = tid >> 1;             // 0..127
            int aq = (tid & 1) * 4;        // 0 or 4
            int grow = block_row + ar;
            float4 av = make_float4(0.f, 0.f, 0.f, 0.f);
            if (grow < M)
                av = *(const float4*)(Ap + (size_t)grow * K + k0 + aq);
            As[aq + 0][ar] = av.x;
            As[aq + 1][ar] = av.y;
            As[aq + 2][ar] = av.z;
            As[aq + 3][ar] = av.w;
            // load W tile (BK x BN); one float4/thread
            int wr = tid >> 5;             // 0..7
            int wc = (tid & 31) * 4;
            *(float4*)&Ws[wr][wc] =
                *(const float4*)(Wp + (size_t)(k0 + wr) * Hc + block_col + wc);
            __syncthreads();

            #pragma unroll
            for (int k = 0; k < BK; k++) {
                float a[TM], w[TN];
                #pragma unroll
                for (int i = 0; i < TM; i++) a[i] = As[k][tr * TM + i];
                #pragma unroll
                for (int j = 0; j < TN; j++) w[j] = Ws[k][tc * TN + j];
                #pragma unroll
                for (int i = 0; i < TM; i++)
                    #pragma unroll
                    for (int j = 0; j < TN; j++)
                        acc[i][j] += a[i] * w[j];
            }
            __syncthreads();
        }
    }

    // epilogue: bias + relu, float4 stores
    #pragma unroll
    for (int i = 0; i < TM; i++) {
        int row = block_row + tr * TM + i;
        if (row >= M) continue;
        #pragma unroll
        for (int j = 0; j < TN; j += 4) {
            int col = block_col + tc * TN + j;
            float4 r;
            r.x = fmaxf(acc[i][j + 0] + bias[col + 0], 0.f);
            r.y = fmaxf(acc[i][j + 1] + bias[col + 1], 0.f);
            r.z = fmaxf(acc[i][j + 2] + bias[col + 2], 0.f);
            r.w = fmaxf(acc[i][j + 3] + bias[col + 3], 0.f);
            *(float4*)(C + (size_t)row * Hc + col) = r;
        }
    }
}

// ---------------- heads: out[n]=rt_n.Wa+ba ; out[N+n]=mv_n.Wm+bm -----------
__global__ void k_heads(const float* __restrict__ Wa, const float* __restrict__ ba,
                        const float* __restrict__ Wm, const float* __restrict__ bm,
                        float* __restrict__ out)
{
    int warp = (blockIdx.x * blockDim.x + threadIdx.x) >> 5;
    int lane = threadIdx.x & 31;
    if (warp >= NNODES) return;
    const float* rrow = g_rt + (size_t)warp * HID;
    const float* mrow = g_mv + (size_t)warp * HID;
    float sa = 0.f, sm = 0.f;
    #pragma unroll
    for (int f = lane; f < HID; f += 32) {
        sa += rrow[f] * __ldg(&Wa[f]);
        sm += mrow[f] * __ldg(&Wm[f]);
    }
    #pragma unroll
    for (int off = 16; off > 0; off >>= 1) {
        sa += __shfl_down_sync(0xffffffffu, sa, off);
        sm += __shfl_down_sync(0xffffffffu, sm, off);
    }
    if (lane == 0) {
        out[warp]          = sa + ba[0];
        out[NNODES + warp] = sm + bm[0];
    }
}

// ---------------- launch ---------------------------------------------------
extern "C" void kernel_launch(void* const* d_in, const int* in_sizes, int n_in,
                              void* d_out, int out_size)
{
    const float* x  = (const float*)d_in[0];
    const void*  ei = d_in[1];
    const float *Wl1 = (const float*)d_in[2],  *bl1 = (const float*)d_in[3],  *Wr1 = (const float*)d_in[4];
    const float *Wl2 = (const float*)d_in[5],  *bl2 = (const float*)d_in[6],  *Wr2 = (const float*)d_in[7];
    const float *Wla = (const float*)d_in[8],  *bla = (const float*)d_in[9],  *Wra = (const float*)d_in[10];
    const float *Wa  = (const float*)d_in[11], *ba  = (const float*)d_in[12];
    const float *Wlm = (const float*)d_in[13], *blm = (const float*)d_in[14], *Wrm = (const float*)d_in[15];
    const float *Wm  = (const float*)d_in[16], *bm  = (const float*)d_in[17];
    float* out = (float*)d_out;

    // symbol addresses for scratch matrices
    float *agg, *h1, *h2, *rt, *mv;
    cudaGetSymbolAddress((void**)&agg, g_agg);
    cudaGetSymbolAddress((void**)&h1,  g_h1);
    cudaGetSymbolAddress((void**)&h2,  g_h2);
    cudaGetSymbolAddress((void**)&rt,  g_rt);
    cudaGetSymbolAddress((void**)&mv,  g_mv);

    // 0) edge dtype detect + 1) CSR build (dst-sorted adjacency)
    k_detect<<<16, 256>>>((const long long*)ei);
    k_zero_counts<<<(NNODES + 255) / 256, 256>>>();
    k_hist<<<(NEDGES + 255) / 256, 256>>>(ei);
    k_scan<<<1, 1024>>>();
    k_copy_wofs<<<(NNODES + 255) / 256, 256>>>();
    k_scatter<<<(NEDGES + 255) / 256, 256>>>(ei);

    dim3 segGrid((NNODES * 32 + 255) / 256);
    dim3 gemmGrid(HID / BN, (NNODES + BM - 1) / BM);

    // 2) layer 1
    k_segmax<FIN><<<segGrid, 256>>>(x, agg);
    k_gemm_fused<<<gemmGrid, 256>>>(agg, Wl1, FIN, x, Wr1, FIN, bl1, h1, NNODES, HID);

    // 3) layer 2
    k_segmax<HID><<<segGrid, 256>>>(h1, agg);
    k_gemm_fused<<<gemmGrid, 256>>>(agg, Wl2, HID, h1, Wr2, HID, bl2, h2, NNODES, HID);

    // 4) layer 3 (shared segmax, two branch GEMMs)
    k_segmax<HID><<<segGrid, 256>>>(h2, agg);
    k_gemm_fused<<<gemmGrid, 256>>>(agg, Wla, HID, h2, Wra, HID, bla, rt, NNODES, HID);
    k_gemm_fused<<<gemmGrid, 256>>>(agg, Wlm, HID, h2, Wrm, HID, blm, mv, NNODES, HID);

    // 5) heads
    k_heads<<<segGrid, 256>>>(Wa, ba, Wm, bm, out);
    (void)in_sizes; (void)n_in; (void)out_size;
}

// round 4
// speedup vs baseline: 1.4704x; 1.4704x over previous
#include <cuda_runtime.h>
#include <float.h>

// Problem constants (fixed shapes)
#define NNODES 50000
#define NEDGES 800000
#define FIN    128
#define HID    256
#define SCAN_BLKS ((NNODES + 255) / 256)   // 196

// ---------------- scratch (device globals; no allocation allowed) ----------
__device__ __align__(256) int   g_counts[NNODES];
__device__ __align__(256) int   g_rowptr[NNODES + 1];
__device__ __align__(256) int   g_wofs[NNODES];
__device__ __align__(256) int   g_ssrc[NEDGES];
__device__ __align__(256) int   g_bsums[SCAN_BLKS];
__device__ __align__(256) int   g_boff[SCAN_BLKS];
__device__ __align__(256) float g_agg[(size_t)NNODES * HID];
__device__ __align__(256) float g_h1 [(size_t)NNODES * HID];
__device__ __align__(256) float g_h2 [(size_t)NNODES * HID];
__device__ __align__(256) float g_rt [(size_t)NNODES * HID];
__device__ __align__(256) float g_mv [(size_t)NNODES * HID];
__device__ int g_use32;   // 1 if edge_index is actually int32 in memory

// ---------------- dtype detection -----------------------------------------
__global__ void k_detect(const long long* __restrict__ ei) {
    int i = blockIdx.x * blockDim.x + threadIdx.x;
    if (i < 4096) {
        long long v = ei[i];
        if (v < 0 || v >= NNODES) atomicExch(&g_use32, 1);
    }
}

__device__ __forceinline__ int edge_at(const void* ei, size_t idx) {
    if (g_use32) return ((const int*)ei)[idx];
    return (int)((const long long*)ei)[idx];
}

// ---------------- CSR build ------------------------------------------------
__global__ void k_zero_counts() {
    int i = blockIdx.x * blockDim.x + threadIdx.x;
    if (i < NNODES) g_counts[i] = 0;
    if (i == 0) g_use32 = 0;
}

__global__ void k_hist(const void* __restrict__ ei) {
    int i = blockIdx.x * blockDim.x + threadIdx.x;
    if (i < NEDGES) {
        int d = edge_at(ei, (size_t)NEDGES + i);   // dst row
        if ((unsigned)d < NNODES) atomicAdd(&g_counts[d], 1);
    }
}

// multi-block scan: per-block inclusive scan
__global__ void k_blockscan() {
    __shared__ int s[256];
    int i = blockIdx.x * 256 + threadIdx.x;
    int v = (i < NNODES) ? g_counts[i] : 0;
    s[threadIdx.x] = v;
    __syncthreads();
    #pragma unroll
    for (int off = 1; off < 256; off <<= 1) {
        int t = (threadIdx.x >= off) ? s[threadIdx.x - off] : 0;
        __syncthreads();
        s[threadIdx.x] += t;
        __syncthreads();
    }
    if (i < NNODES) g_rowptr[i + 1] = s[threadIdx.x];
    if (threadIdx.x == 255) g_bsums[blockIdx.x] = s[255];
}

// scan the block sums (one block; SCAN_BLKS=196 <= 256)
__global__ void k_scanbs() {
    __shared__ int s[256];
    int t = threadIdx.x;
    s[t] = (t < SCAN_BLKS) ? g_bsums[t] : 0;
    __syncthreads();
    #pragma unroll
    for (int off = 1; off < 256; off <<= 1) {
        int v = (t >= off) ? s[t - off] : 0;
        __syncthreads();
        s[t] += v;
        __syncthreads();
    }
    if (t < SCAN_BLKS) g_boff[t] = (t == 0) ? 0 : s[t - 1];
}

__global__ void k_addoff() {
    int i = blockIdx.x * 256 + threadIdx.x;
    if (i < NNODES) g_rowptr[i + 1] += g_boff[blockIdx.x];
    if (i == 0) g_rowptr[0] = 0;
}

__global__ void k_copy_wofs() {
    int i = blockIdx.x * blockDim.x + threadIdx.x;
    if (i < NNODES) g_wofs[i] = g_rowptr[i];
}

__global__ void k_scatter(const void* __restrict__ ei) {
    int i = blockIdx.x * blockDim.x + threadIdx.x;
    if (i < NEDGES) {
        int s = edge_at(ei, i);
        int d = edge_at(ei, (size_t)NEDGES + i);
        if ((unsigned)d >= NNODES || (unsigned)s >= NNODES) return;
        int p = atomicAdd(&g_wofs[d], 1);
        if (p < NEDGES) g_ssrc[p] = s;
    }
}

// ---------------- segment max (one warp per node, float4 lanes) ------------
__device__ __forceinline__ float4 f4max(float4 a, float4 b) {
    return make_float4(fmaxf(a.x, b.x), fmaxf(a.y, b.y),
                       fmaxf(a.z, b.z), fmaxf(a.w, b.w));
}

template <int F>
__global__ void k_segmax(const float* __restrict__ feat, float* __restrict__ out) {
    constexpr int VPL = F / 128;
    int warp = (blockIdx.x * blockDim.x + threadIdx.x) >> 5;
    int lane = threadIdx.x & 31;
    if (warp >= NNODES) return;
    int beg = g_rowptr[warp];
    int end = g_rowptr[warp + 1];

    float4 acc[VPL];
    #pragma unroll
    for (int v = 0; v < VPL; v++)
        acc[v] = make_float4(-FLT_MAX, -FLT_MAX, -FLT_MAX, -FLT_MAX);

    int e = beg;
    for (; e + 1 < end; e += 2) {
        int s0 = g_ssrc[e], s1 = g_ssrc[e + 1];
        const float4* r0 = (const float4*)(feat + (size_t)s0 * F);
        const float4* r1 = (const float4*)(feat + (size_t)s1 * F);
        #pragma unroll
        for (int v = 0; v < VPL; v++) {
            float4 a = __ldg(&r0[v * 32 + lane]);
            float4 b = __ldg(&r1[v * 32 + lane]);
            acc[v] = f4max(acc[v], f4max(a, b));
        }
    }
    if (e < end) {
        int s0 = g_ssrc[e];
        const float4* r0 = (const float4*)(feat + (size_t)s0 * F);
        #pragma unroll
        for (int v = 0; v < VPL; v++)
            acc[v] = f4max(acc[v], __ldg(&r0[v * 32 + lane]));
    }
    if (beg == end) {
        #pragma unroll
        for (int v = 0; v < VPL; v++)
            acc[v] = make_float4(0.f, 0.f, 0.f, 0.f);
    }
    float4* orow = (float4*)(out + (size_t)warp * F);
    #pragma unroll
    for (int v = 0; v < VPL; v++)
        orow[v * 32 + lane] = acc[v];
}

// ---------------- TF32 tensor-core fused GEMM ------------------------------
// C = relu(A@WA + B@WB + bias). 3xTF32 split for fp32-level accuracy.
// Block 128x128, BK=16, 8 warps (2x4), warp tile 64x32, m16n8k8 mma.

#define GBM 128
#define GBN 128
#define GBK 16
#define ASTR 20      // As row stride (floats): conflict-free for a-frag pattern
#define WSTR 136     // Ws row stride (floats): conflict-free for b-frag pattern

__device__ __forceinline__ unsigned f2tf32(float x) {
    unsigned r;
    asm("cvt.rna.tf32.f32 %0, %1;" : "=r"(r) : "f"(x));
    return r;
}

__device__ __forceinline__ void mma_tf32(float* c, const unsigned* a, const unsigned* b) {
    asm volatile(
        "mma.sync.aligned.m16n8k8.row.col.f32.tf32.tf32.f32 "
        "{%0,%1,%2,%3}, {%4,%5,%6,%7}, {%8,%9}, {%0,%1,%2,%3};"
        : "+f"(c[0]), "+f"(c[1]), "+f"(c[2]), "+f"(c[3])
        : "r"(a[0]), "r"(a[1]), "r"(a[2]), "r"(a[3]), "r"(b[0]), "r"(b[1]));
}

__device__ __forceinline__ void cp16(void* dst, const void* src) {
    unsigned d = (unsigned)__cvta_generic_to_shared(dst);
    asm volatile("cp.async.cg.shared.global [%0], [%1], 16;" :: "r"(d), "l"(src));
}

__global__ __launch_bounds__(256)
void k_gemm_mma(const float* __restrict__ A, const float* __restrict__ WA, int KA,
                const float* __restrict__ B, const float* __restrict__ WB, int KB,
                const float* __restrict__ bias, float* __restrict__ C, int M)
{
    __shared__ float As[2][GBM][ASTR];
    __shared__ float Ws[2][GBK][WSTR];

    int tid = threadIdx.x, lane = tid & 31, w = tid >> 5;
    int wm = w >> 2, wn = w & 3;
    int brow = blockIdx.y * GBM, bcol = blockIdx.x * GBN;

    float acc[4][4][4];
    #pragma unroll
    for (int i = 0; i < 4; i++)
        #pragma unroll
        for (int j = 0; j < 4; j++)
            #pragma unroll
            for (int q = 0; q < 4; q++) acc[i][j][q] = 0.f;

    int itA = KA / GBK, itB = KB / GBK;
    int iters = itA + itB;

    auto load_stage = [&](int it, int buf) {
        int ph = (it >= itA);
        const float* Ap = ph ? B : A;
        const float* Wp = ph ? WB : WA;
        int K = ph ? KB : KA;
        int k0 = (ph ? it - itA : it) * GBK;
        #pragma unroll
        for (int j = 0; j < 2; j++) {           // A: 512 float4
            int id = tid + j * 256;
            int r = id >> 2, c4 = id & 3;
            int rg = brow + r; if (rg > M - 1) rg = M - 1;
            cp16(&As[buf][r][c4 * 4], Ap + (size_t)rg * K + k0 + c4 * 4);
        }
        #pragma unroll
        for (int j = 0; j < 2; j++) {           // W: 512 float4
            int id = tid + j * 256;
            int kr = id >> 5, c4 = id & 31;
            cp16(&Ws[buf][kr][c4 * 4], Wp + (size_t)(k0 + kr) * HID + bcol + c4 * 4);
        }
    };

    load_stage(0, 0);
    asm volatile("cp.async.commit_group;");

    for (int it = 0; it < iters; ++it) {
        int buf = it & 1;
        if (it + 1 < iters) {
            load_stage(it + 1, buf ^ 1);
            asm volatile("cp.async.commit_group;");
            asm volatile("cp.async.wait_group 1;");
        } else {
            asm volatile("cp.async.wait_group 0;");
        }
        __syncthreads();

        #pragma unroll
        for (int ks = 0; ks < GBK / 8; ks++) {
            int kb = ks * 8;
            unsigned bh[4][2], bl[4][2];
            #pragma unroll
            for (int nf = 0; nf < 4; nf++) {
                int nc = wn * 32 + nf * 8 + (lane >> 2);
                float b0 = Ws[buf][kb + (lane & 3)][nc];
                float b1 = Ws[buf][kb + (lane & 3) + 4][nc];
                bh[nf][0] = f2tf32(b0);
                bl[nf][0] = f2tf32(b0 - __uint_as_float(bh[nf][0]));
                bh[nf][1] = f2tf32(b1);
                bl[nf][1] = f2tf32(b1 - __uint_as_float(bh[nf][1]));
            }
            #pragma unroll
            for (int mf = 0; mf < 4; mf++) {
                int mr = wm * 64 + mf * 16 + (lane >> 2);
                float a0 = As[buf][mr][kb + (lane & 3)];
                float a1 = As[buf][mr + 8][kb + (lane & 3)];
                float a2 = As[buf][mr][kb + (lane & 3) + 4];
                float a3 = As[buf][mr + 8][kb + (lane & 3) + 4];
                unsigned ah[4], al[4];
                ah[0] = f2tf32(a0); al[0] = f2tf32(a0 - __uint_as_float(ah[0]));
                ah[1] = f2tf32(a1); al[1] = f2tf32(a1 - __uint_as_float(ah[1]));
                ah[2] = f2tf32(a2); al[2] = f2tf32(a2 - __uint_as_float(ah[2]));
                ah[3] = f2tf32(a3); al[3] = f2tf32(a3 - __uint_as_float(ah[3]));
                #pragma unroll
                for (int nf = 0; nf < 4; nf++) {
                    mma_tf32(acc[mf][nf], ah, bh[nf]);
                    mma_tf32(acc[mf][nf], al, bh[nf]);
                    mma_tf32(acc[mf][nf], ah, bl[nf]);
                }
            }
        }
        __syncthreads();
    }

    // epilogue: bias + relu
    #pragma unroll
    for (int mf = 0; mf < 4; mf++) {
        int r0 = brow + wm * 64 + mf * 16 + (lane >> 2);
        #pragma unroll
        for (int nf = 0; nf < 4; nf++) {
            int c0 = bcol + wn * 32 + nf * 8 + (lane & 3) * 2;
            float bx = __ldg(&bias[c0]), by = __ldg(&bias[c0 + 1]);
            if (r0 < M) {
                float2 v = make_float2(fmaxf(acc[mf][nf][0] + bx, 0.f),
                                       fmaxf(acc[mf][nf][1] + by, 0.f));
                *(float2*)(C + (size_t)r0 * HID + c0) = v;
            }
            if (r0 + 8 < M) {
                float2 v = make_float2(fmaxf(acc[mf][nf][2] + bx, 0.f),
                                       fmaxf(acc[mf][nf][3] + by, 0.f));
                *(float2*)(C + (size_t)(r0 + 8) * HID + c0) = v;
            }
        }
    }
}

// ---------------- heads: out[n]=rt_n.Wa+ba ; out[N+n]=mv_n.Wm+bm -----------
__global__ void k_heads(const float* __restrict__ Wa, const float* __restrict__ ba,
                        const float* __restrict__ Wm, const float* __restrict__ bm,
                        float* __restrict__ out)
{
    int warp = (blockIdx.x * blockDim.x + threadIdx.x) >> 5;
    int lane = threadIdx.x & 31;
    if (warp >= NNODES) return;
    const float* rrow = g_rt + (size_t)warp * HID;
    const float* mrow = g_mv + (size_t)warp * HID;
    float sa = 0.f, sm = 0.f;
    #pragma unroll
    for (int f = lane; f < HID; f += 32) {
        sa += rrow[f] * __ldg(&Wa[f]);
        sm += mrow[f] * __ldg(&Wm[f]);
    }
    #pragma unroll
    for (int off = 16; off > 0; off >>= 1) {
        sa += __shfl_down_sync(0xffffffffu, sa, off);
        sm += __shfl_down_sync(0xffffffffu, sm, off);
    }
    if (lane == 0) {
        out[warp]          = sa + ba[0];
        out[NNODES + warp] = sm + bm[0];
    }
}

// ---------------- launch ---------------------------------------------------
extern "C" void kernel_launch(void* const* d_in, const int* in_sizes, int n_in,
                              void* d_out, int out_size)
{
    const float* x  = (const float*)d_in[0];
    const void*  ei = d_in[1];
    const float *Wl1 = (const float*)d_in[2],  *bl1 = (const float*)d_in[3],  *Wr1 = (const float*)d_in[4];
    const float *Wl2 = (const float*)d_in[5],  *bl2 = (const float*)d_in[6],  *Wr2 = (const float*)d_in[7];
    const float *Wla = (const float*)d_in[8],  *bla = (const float*)d_in[9],  *Wra = (const float*)d_in[10];
    const float *Wa  = (const float*)d_in[11], *ba  = (const float*)d_in[12];
    const float *Wlm = (const float*)d_in[13], *blm = (const float*)d_in[14], *Wrm = (const float*)d_in[15];
    const float *Wm  = (const float*)d_in[16], *bm  = (const float*)d_in[17];
    float* out = (float*)d_out;

    float *agg, *h1, *h2, *rt, *mv;
    cudaGetSymbolAddress((void**)&agg, g_agg);
    cudaGetSymbolAddress((void**)&h1,  g_h1);
    cudaGetSymbolAddress((void**)&h2,  g_h2);
    cudaGetSymbolAddress((void**)&rt,  g_rt);
    cudaGetSymbolAddress((void**)&mv,  g_mv);

    // 0) zero + dtype detect, 1) CSR build
    k_zero_counts<<<SCAN_BLKS, 256>>>();
    k_detect<<<16, 256>>>((const long long*)ei);
    k_hist<<<(NEDGES + 255) / 256, 256>>>(ei);
    k_blockscan<<<SCAN_BLKS, 256>>>();
    k_scanbs<<<1, 256>>>();
    k_addoff<<<SCAN_BLKS, 256>>>();
    k_copy_wofs<<<SCAN_BLKS, 256>>>();
    k_scatter<<<(NEDGES + 255) / 256, 256>>>(ei);

    dim3 segGrid((NNODES * 32 + 255) / 256);
    dim3 gemmGrid(HID / GBN, (NNODES + GBM - 1) / GBM);

    // 2) layer 1
    k_segmax<FIN><<<segGrid, 256>>>(x, agg);
    k_gemm_mma<<<gemmGrid, 256>>>(agg, Wl1, FIN, x, Wr1, FIN, bl1, h1, NNODES);

    // 3) layer 2
    k_segmax<HID><<<segGrid, 256>>>(h1, agg);
    k_gemm_mma<<<gemmGrid, 256>>>(agg, Wl2, HID, h1, Wr2, HID, bl2, h2, NNODES);

    // 4) layer 3 (shared segmax, two branch GEMMs)
    k_segmax<HID><<<segGrid, 256>>>(h2, agg);
    k_gemm_mma<<<gemmGrid, 256>>>(agg, Wla, HID, h2, Wra, HID, bla, rt, NNODES);
    k_gemm_mma<<<gemmGrid, 256>>>(agg, Wlm, HID, h2, Wrm, HID, blm, mv, NNODES);

    // 5) heads
    k_heads<<<segGrid, 256>>>(Wa, ba, Wm, bm, out);
    (void)in_sizes; (void)n_in; (void)out_size;
}

// round 6
// speedup vs baseline: 1.4925x; 1.0150x over previous
#include <cuda_runtime.h>
#include <float.h>

// Problem constants (fixed shapes)
#define NNODES 50000
#define NEDGES 800000
#define FIN    128
#define HID    256
#define SCAN_BLKS ((NNODES + 255) / 256)   // 196

// ---------------- scratch (device globals; no allocation allowed) ----------
__device__ __align__(256) int   g_counts[NNODES];        // zero-init at load; re-zeroed in k_blockscan
__device__ __align__(256) int   g_rowptr[NNODES + 1];
__device__ __align__(256) int   g_wofs[NNODES];
__device__ __align__(256) int   g_ssrc[NEDGES];
__device__ __align__(256) int   g_bsums[SCAN_BLKS];
__device__ __align__(256) float g_agg[(size_t)NNODES * HID];
__device__ __align__(256) float g_h1 [(size_t)NNODES * HID];
__device__ __align__(256) float g_h2 [(size_t)NNODES * HID];
__device__ __align__(256) float g_rt [(size_t)NNODES * HID];
__device__ __align__(256) float g_mv [(size_t)NNODES * HID];
__device__ int g_use32 = 0;   // 1 if edge_index is actually int32 in memory
                              // (input-constant across calls -> set-once is deterministic)

// ---------------- dtype detection -----------------------------------------
__global__ void k_detect(const long long* __restrict__ ei) {
    int i = blockIdx.x * blockDim.x + threadIdx.x;
    if (i < 4096) {
        long long v = ei[i];
        if (v < 0 || v >= NNODES) atomicExch(&g_use32, 1);
    }
}

__device__ __forceinline__ int edge_at(const void* ei, size_t idx) {
    if (g_use32) return ((const int*)ei)[idx];
    return (int)((const long long*)ei)[idx];
}

// ---------------- CSR build ------------------------------------------------
__global__ void k_hist(const void* __restrict__ ei) {
    int i = blockIdx.x * blockDim.x + threadIdx.x;
    if (i < NEDGES) {
        int d = edge_at(ei, (size_t)NEDGES + i);   // dst row
        if ((unsigned)d < NNODES) atomicAdd(&g_counts[d], 1);
    }
}

// per-block inclusive scan; also re-zeroes counts for the next graph replay
__global__ void k_blockscan() {
    __shared__ int s[256];
    int i = blockIdx.x * 256 + threadIdx.x;
    int v = (i < NNODES) ? g_counts[i] : 0;
    if (i < NNODES) g_counts[i] = 0;          // reset for next call
    s[threadIdx.x] = v;
    __syncthreads();
    #pragma unroll
    for (int off = 1; off < 256; off <<= 1) {
        int t = (threadIdx.x >= off) ? s[threadIdx.x - off] : 0;
        __syncthreads();
        s[threadIdx.x] += t;
        __syncthreads();
    }
    if (i < NNODES) g_rowptr[i + 1] = s[threadIdx.x];
    if (threadIdx.x == 255) g_bsums[blockIdx.x] = s[255];
}

// single block: scan block sums, apply offsets, emit wofs
__global__ void k_scanfix() {
    __shared__ int s[256];
    __shared__ int boff[SCAN_BLKS];
    int t = threadIdx.x;
    s[t] = (t < SCAN_BLKS) ? g_bsums[t] : 0;
    __syncthreads();
    #pragma unroll
    for (int off = 1; off < 256; off <<= 1) {
        int v = (t >= off) ? s[t - off] : 0;
        __syncthreads();
        s[t] += v;
        __syncthreads();
    }
    if (t < SCAN_BLKS) boff[t] = (t == 0) ? 0 : s[t - 1];
    __syncthreads();
    for (int i = t; i < NNODES; i += 256) {
        int v = g_rowptr[i + 1] + boff[i >> 8];
        g_rowptr[i + 1] = v;
        if (i + 1 < NNODES) g_wofs[i + 1] = v;
    }
    if (t == 0) { g_rowptr[0] = 0; g_wofs[0] = 0; }
}

__global__ void k_scatter(const void* __restrict__ ei) {
    int i = blockIdx.x * blockDim.x + threadIdx.x;
    if (i < NEDGES) {
        int s = edge_at(ei, i);
        int d = edge_at(ei, (size_t)NEDGES + i);
        if ((unsigned)d >= NNODES || (unsigned)s >= NNODES) return;
        int p = atomicAdd(&g_wofs[d], 1);
        if (p < NEDGES) g_ssrc[p] = s;
    }
}

// ---------------- segment max (one warp per node, 4-edge unroll) -----------
__device__ __forceinline__ float4 f4max(float4 a, float4 b) {
    return make_float4(fmaxf(a.x, b.x), fmaxf(a.y, b.y),
                       fmaxf(a.z, b.z), fmaxf(a.w, b.w));
}

template <int F>
__global__ void k_segmax(const float* __restrict__ feat, float* __restrict__ out) {
    constexpr int VPL = F / 128;
    int warp = (blockIdx.x * blockDim.x + threadIdx.x) >> 5;
    int lane = threadIdx.x & 31;
    if (warp >= NNODES) return;
    int beg = __ldg(&g_rowptr[warp]);
    int end = __ldg(&g_rowptr[warp + 1]);

    float4 acc[VPL];
    #pragma unroll
    for (int v = 0; v < VPL; v++)
        acc[v] = make_float4(-FLT_MAX, -FLT_MAX, -FLT_MAX, -FLT_MAX);

    int e = beg;
    for (; e + 3 < end; e += 4) {
        int s0 = __ldg(&g_ssrc[e]);
        int s1 = __ldg(&g_ssrc[e + 1]);
        int s2 = __ldg(&g_ssrc[e + 2]);
        int s3 = __ldg(&g_ssrc[e + 3]);
        const float4* r0 = (const float4*)(feat + (size_t)s0 * F);
        const float4* r1 = (const float4*)(feat + (size_t)s1 * F);
        const float4* r2 = (const float4*)(feat + (size_t)s2 * F);
        const float4* r3 = (const float4*)(feat + (size_t)s3 * F);
        #pragma unroll
        for (int v = 0; v < VPL; v++) {
            float4 a = __ldg(&r0[v * 32 + lane]);
            float4 b = __ldg(&r1[v * 32 + lane]);
            float4 c = __ldg(&r2[v * 32 + lane]);
            float4 d = __ldg(&r3[v * 32 + lane]);
            acc[v] = f4max(acc[v], f4max(f4max(a, b), f4max(c, d)));
        }
    }
    for (; e < end; e++) {
        int s0 = __ldg(&g_ssrc[e]);
        const float4* r0 = (const float4*)(feat + (size_t)s0 * F);
        #pragma unroll
        for (int v = 0; v < VPL; v++)
            acc[v] = f4max(acc[v], __ldg(&r0[v * 32 + lane]));
    }
    if (beg == end) {
        #pragma unroll
        for (int v = 0; v < VPL; v++)
            acc[v] = make_float4(0.f, 0.f, 0.f, 0.f);
    }
    float4* orow = (float4*)(out + (size_t)warp * F);
    #pragma unroll
    for (int v = 0; v < VPL; v++)
        orow[v * 32 + lane] = acc[v];
}

// ---------------- TF32 tensor-core fused GEMM ------------------------------
// C = relu(A@WA + B@WB + bias). 3xTF32 split for fp32-level accuracy.
// Block 128x128, BK=16, 8 warps (2x4), warp tile 64x32, m16n8k8 mma.

#define GBM 128
#define GBN 128
#define GBK 16
#define ASTR 20
#define WSTR 136

__device__ __forceinline__ unsigned f2tf32(float x) {
    unsigned r;
    asm("cvt.rna.tf32.f32 %0, %1;" : "=r"(r) : "f"(x));
    return r;
}

__device__ __forceinline__ void mma_tf32(float* c, const unsigned* a, const unsigned* b) {
    asm volatile(
        "mma.sync.aligned.m16n8k8.row.col.f32.tf32.tf32.f32 "
        "{%0,%1,%2,%3}, {%4,%5,%6,%7}, {%8,%9}, {%0,%1,%2,%3};"
        : "+f"(c[0]), "+f"(c[1]), "+f"(c[2]), "+f"(c[3])
        : "r"(a[0]), "r"(a[1]), "r"(a[2]), "r"(a[3]), "r"(b[0]), "r"(b[1]));
}

__device__ __forceinline__ void cp16(void* dst, const void* src) {
    unsigned d = (unsigned)__cvta_generic_to_shared(dst);
    asm volatile("cp.async.cg.shared.global [%0], [%1], 16;" :: "r"(d), "l"(src));
}

__global__ __launch_bounds__(256, 2)
void k_gemm_mma(const float* __restrict__ A, const float* __restrict__ WA, int KA,
                const float* __restrict__ B, const float* __restrict__ WB, int KB,
                const float* __restrict__ bias, float* __restrict__ C, int M)
{
    __shared__ float As[2][GBM][ASTR];
    __shared__ float Ws[2][GBK][WSTR];

    int tid = threadIdx.x, lane = tid & 31, w = tid >> 5;
    int wm = w >> 2, wn = w & 3;
    int brow = blockIdx.y * GBM, bcol = blockIdx.x * GBN;

    float acc[4][4][4];
    #pragma unroll
    for (int i = 0; i < 4; i++)
        #pragma unroll
        for (int j = 0; j < 4; j++)
            #pragma unroll
            for (int q = 0; q < 4; q++) acc[i][j][q] = 0.f;

    int itA = KA / GBK, itB = KB / GBK;
    int iters = itA + itB;

    auto load_stage = [&](int it, int buf) {
        int ph = (it >= itA);
        const float* Ap = ph ? B : A;
        const float* Wp = ph ? WB : WA;
        int K = ph ? KB : KA;
        int k0 = (ph ? it - itA : it) * GBK;
        #pragma unroll
        for (int j = 0; j < 2; j++) {
            int id = tid + j * 256;
            int r = id >> 2, c4 = id & 3;
            int rg = brow + r; if (rg > M - 1) rg = M - 1;
            cp16(&As[buf][r][c4 * 4], Ap + (size_t)rg * K + k0 + c4 * 4);
        }
        #pragma unroll
        for (int j = 0; j < 2; j++) {
            int id = tid + j * 256;
            int kr = id >> 5, c4 = id & 31;
            cp16(&Ws[buf][kr][c4 * 4], Wp + (size_t)(k0 + kr) * HID + bcol + c4 * 4);
        }
    };

    load_stage(0, 0);
    asm volatile("cp.async.commit_group;");

    for (int it = 0; it < iters; ++it) {
        int buf = it & 1;
        if (it + 1 < iters) {
            load_stage(it + 1, buf ^ 1);
            asm volatile("cp.async.commit_group;");
            asm volatile("cp.async.wait_group 1;");
        } else {
            asm volatile("cp.async.wait_group 0;");
        }
        __syncthreads();

        #pragma unroll
        for (int ks = 0; ks < GBK / 8; ks++) {
            int kb = ks * 8;
            unsigned bh[4][2], bl[4][2];
            #pragma unroll
            for (int nf = 0; nf < 4; nf++) {
                int nc = wn * 32 + nf * 8 + (lane >> 2);
                float b0 = Ws[buf][kb + (lane & 3)][nc];
                float b1 = Ws[buf][kb + (lane & 3) + 4][nc];
                bh[nf][0] = f2tf32(b0);
                bl[nf][0] = f2tf32(b0 - __uint_as_float(bh[nf][0]));
                bh[nf][1] = f2tf32(b1);
                bl[nf][1] = f2tf32(b1 - __uint_as_float(bh[nf][1]));
            }
            #pragma unroll
            for (int mf = 0; mf < 4; mf++) {
                int mr = wm * 64 + mf * 16 + (lane >> 2);
                float a0 = As[buf][mr][kb + (lane & 3)];
                float a1 = As[buf][mr + 8][kb + (lane & 3)];
                float a2 = As[buf][mr][kb + (lane & 3) + 4];
                float a3 = As[buf][mr + 8][kb + (lane & 3) + 4];
                unsigned ah[4], al[4];
                ah[0] = f2tf32(a0); al[0] = f2tf32(a0 - __uint_as_float(ah[0]));
                ah[1] = f2tf32(a1); al[1] = f2tf32(a1 - __uint_as_float(ah[1]));
                ah[2] = f2tf32(a2); al[2] = f2tf32(a2 - __uint_as_float(ah[2]));
                ah[3] = f2tf32(a3); al[3] = f2tf32(a3 - __uint_as_float(ah[3]));
                #pragma unroll
                for (int nf = 0; nf < 4; nf++) {
                    mma_tf32(acc[mf][nf], ah, bh[nf]);
                    mma_tf32(acc[mf][nf], al, bh[nf]);
                    mma_tf32(acc[mf][nf], ah, bl[nf]);
                }
            }
        }
        __syncthreads();
    }

    #pragma unroll
    for (int mf = 0; mf < 4; mf++) {
        int r0 = brow + wm * 64 + mf * 16 + (lane >> 2);
        #pragma unroll
        for (int nf = 0; nf < 4; nf++) {
            int c0 = bcol + wn * 32 + nf * 8 + (lane & 3) * 2;
            float bx = __ldg(&bias[c0]), by = __ldg(&bias[c0 + 1]);
            if (r0 < M) {
                float2 v = make_float2(fmaxf(acc[mf][nf][0] + bx, 0.f),
                                       fmaxf(acc[mf][nf][1] + by, 0.f));
                *(float2*)(C + (size_t)r0 * HID + c0) = v;
            }
            if (r0 + 8 < M) {
                float2 v = make_float2(fmaxf(acc[mf][nf][2] + bx, 0.f),
                                       fmaxf(acc[mf][nf][3] + by, 0.f));
                *(float2*)(C + (size_t)(r0 + 8) * HID + c0) = v;
            }
        }
    }
}

// ---------------- heads ----------------------------------------------------
__global__ void k_heads(const float* __restrict__ Wa, const float* __restrict__ ba,
                        const float* __restrict__ Wm, const float* __restrict__ bm,
                        float* __restrict__ out)
{
    int warp = (blockIdx.x * blockDim.x + threadIdx.x) >> 5;
    int lane = threadIdx.x & 31;
    if (warp >= NNODES) return;
    const float* rrow = g_rt + (size_t)warp * HID;
    const float* mrow = g_mv + (size_t)warp * HID;
    float sa = 0.f, sm = 0.f;
    #pragma unroll
    for (int f = lane; f < HID; f += 32) {
        sa += rrow[f] * __ldg(&Wa[f]);
        sm += mrow[f] * __ldg(&Wm[f]);
    }
    #pragma unroll
    for (int off = 16; off > 0; off >>= 1) {
        sa += __shfl_down_sync(0xffffffffu, sa, off);
        sm += __shfl_down_sync(0xffffffffu, sm, off);
    }
    if (lane == 0) {
        out[warp]          = sa + ba[0];
        out[NNODES + warp] = sm + bm[0];
    }
}

// ---------------- launch ---------------------------------------------------
extern "C" void kernel_launch(void* const* d_in, const int* in_sizes, int n_in,
                              void* d_out, int out_size)
{
    const float* x  = (const float*)d_in[0];
    const void*  ei = d_in[1];
    const float *Wl1 = (const float*)d_in[2],  *bl1 = (const float*)d_in[3],  *Wr1 = (const float*)d_in[4];
    const float *Wl2 = (const float*)d_in[5],  *bl2 = (const float*)d_in[6],  *Wr2 = (const float*)d_in[7];
    const float *Wla = (const float*)d_in[8],  *bla = (const float*)d_in[9],  *Wra = (const float*)d_in[10];
    const float *Wa  = (const float*)d_in[11], *ba  = (const float*)d_in[12];
    const float *Wlm = (const float*)d_in[13], *blm = (const float*)d_in[14], *Wrm = (const float*)d_in[15];
    const float *Wm  = (const float*)d_in[16], *bm  = (const float*)d_in[17];
    float* out = (float*)d_out;

    float *agg, *h1, *h2, *rt, *mv;
    cudaGetSymbolAddress((void**)&agg, g_agg);
    cudaGetSymbolAddress((void**)&h1,  g_h1);
    cudaGetSymbolAddress((void**)&h2,  g_h2);
    cudaGetSymbolAddress((void**)&rt,  g_rt);
    cudaGetSymbolAddress((void**)&mv,  g_mv);

    // CSR build: launches 0..4 (segmax lands at index 5 for ncu -s 5)
    k_detect<<<16, 256>>>((const long long*)ei);
    k_hist<<<(NEDGES + 255) / 256, 256>>>(ei);
    k_blockscan<<<SCAN_BLKS, 256>>>();
    k_scanfix<<<1, 256>>>();
    k_scatter<<<(NEDGES + 255) / 256, 256>>>(ei);

    dim3 segGrid((NNODES * 32 + 255) / 256);
    dim3 gemmGrid(HID / GBN, (NNODES + GBM - 1) / GBM);

    // layer 1
    k_segmax<FIN><<<segGrid, 256>>>(x, agg);
    k_gemm_mma<<<gemmGrid, 256>>>(agg, Wl1, FIN, x, Wr1, FIN, bl1, h1, NNODES);

    // layer 2
    k_segmax<HID><<<segGrid, 256>>>(h1, agg);
    k_gemm_mma<<<gemmGrid, 256>>>(agg, Wl2, HID, h1, Wr2, HID, bl2, h2, NNODES);

    // layer 3 (shared segmax, two branch GEMMs)
    k_segmax<HID><<<segGrid, 256>>>(h2, agg);
    k_gemm_mma<<<gemmGrid, 256>>>(agg, Wla, HID, h2, Wra, HID, bla, rt, NNODES);
    k_gemm_mma<<<gemmGrid, 256>>>(agg, Wlm, HID, h2, Wrm, HID, blm, mv, NNODES);

    // heads
    k_heads<<<segGrid, 256>>>(Wa, ba, Wm, bm, out);
    (void)in_sizes; (void)n_in; (void)out_size;
}

// round 8
// speedup vs baseline: 1.7322x; 1.1606x over previous
#include <cuda_runtime.h>
#include <float.h>

// Problem constants (fixed shapes)
#define NNODES 50000
#define NEDGES 800000
#define FIN    128
#define HID    256
#define SCAN_BLKS ((NNODES + 255) / 256)   // 196

// ---------------- scratch (device globals; no allocation allowed) ----------
__device__ __align__(256) int   g_counts[NNODES];        // zero-init; re-zeroed in k_blockscan
__device__ __align__(256) int   g_rowptr[NNODES + 1];
__device__ __align__(256) int   g_wofs[NNODES];
__device__ __align__(256) int   g_ssrc[NEDGES];
__device__ __align__(256) int   g_bsums[SCAN_BLKS];
__device__ __align__(256) int   g_boff[SCAN_BLKS];
__device__ __align__(256) float g_agg[(size_t)NNODES * HID];
__device__ __align__(256) float g_h1 [(size_t)NNODES * HID];
__device__ __align__(256) float g_h2 [(size_t)NNODES * HID];
__device__ __align__(256) float g_rt [(size_t)NNODES * HID];
__device__ __align__(256) float g_mv [(size_t)NNODES * HID];
__device__ int g_use32 = 0;   // 1 if edge_index is actually int32 in memory

// ---------------- dtype detection -----------------------------------------
__global__ void k_detect(const long long* __restrict__ ei) {
    int i = blockIdx.x * blockDim.x + threadIdx.x;
    if (i < 4096) {
        long long v = ei[i];
        if (v < 0 || v >= NNODES) atomicExch(&g_use32, 1);
    }
}

__device__ __forceinline__ int edge_at(const void* ei, size_t idx) {
    if (g_use32) return ((const int*)ei)[idx];
    return (int)((const long long*)ei)[idx];
}

// ---------------- CSR build ------------------------------------------------
__global__ void k_hist(const void* __restrict__ ei) {
    int i = blockIdx.x * blockDim.x + threadIdx.x;
    if (i < NEDGES) {
        int d = edge_at(ei, (size_t)NEDGES + i);
        if ((unsigned)d < NNODES) atomicAdd(&g_counts[d], 1);
    }
}

// per-block inclusive scan; also re-zeroes counts for the next graph replay
__global__ void k_blockscan() {
    __shared__ int s[256];
    int i = blockIdx.x * 256 + threadIdx.x;
    int v = (i < NNODES) ? g_counts[i] : 0;
    if (i < NNODES) g_counts[i] = 0;
    s[threadIdx.x] = v;
    __syncthreads();
    #pragma unroll
    for (int off = 1; off < 256; off <<= 1) {
        int t = (threadIdx.x >= off) ? s[threadIdx.x - off] : 0;
        __syncthreads();
        s[threadIdx.x] += t;
        __syncthreads();
    }
    if (i < NNODES) g_rowptr[i + 1] = s[threadIdx.x];
    if (threadIdx.x == 255) g_bsums[blockIdx.x] = s[255];
}

// one small block: scan only the 196 block sums
__global__ void k_scanbs() {
    __shared__ int s[256];
    int t = threadIdx.x;
    s[t] = (t < SCAN_BLKS) ? g_bsums[t] : 0;
    __syncthreads();
    #pragma unroll
    for (int off = 1; off < 256; off <<= 1) {
        int v = (t >= off) ? s[t - off] : 0;
        __syncthreads();
        s[t] += v;
        __syncthreads();
    }
    if (t < SCAN_BLKS) g_boff[t] = (t == 0) ? 0 : s[t - 1];
}

// parallel offset apply + wofs emit (196 blocks)
__global__ void k_applyoff() {
    int i = blockIdx.x * 256 + threadIdx.x;
    if (i < NNODES) {
        int v = g_rowptr[i + 1] + g_boff[blockIdx.x];
        g_rowptr[i + 1] = v;
        if (i + 1 < NNODES) g_wofs[i + 1] = v;
    }
    if (i == 0) { g_rowptr[0] = 0; g_wofs[0] = 0; }
}

__global__ void k_scatter(const void* __restrict__ ei) {
    int i = blockIdx.x * blockDim.x + threadIdx.x;
    if (i < NEDGES) {
        int s = edge_at(ei, i);
        int d = edge_at(ei, (size_t)NEDGES + i);
        if ((unsigned)d >= NNODES || (unsigned)s >= NNODES) return;
        int p = atomicAdd(&g_wofs[d], 1);
        if (p < NEDGES) g_ssrc[p] = s;
    }
}

// ---------------- segment max (one warp per node, 4-edge unroll) -----------
__device__ __forceinline__ float4 f4max(float4 a, float4 b) {
    return make_float4(fmaxf(a.x, b.x), fmaxf(a.y, b.y),
                       fmaxf(a.z, b.z), fmaxf(a.w, b.w));
}

template <int F>
__global__ void k_segmax(const float* __restrict__ feat, float* __restrict__ out) {
    constexpr int VPL = F / 128;
    int warp = (blockIdx.x * blockDim.x + threadIdx.x) >> 5;
    int lane = threadIdx.x & 31;
    if (warp >= NNODES) return;
    int beg = __ldg(&g_rowptr[warp]);
    int end = __ldg(&g_rowptr[warp + 1]);

    float4 acc[VPL];
    #pragma unroll
    for (int v = 0; v < VPL; v++)
        acc[v] = make_float4(-FLT_MAX, -FLT_MAX, -FLT_MAX, -FLT_MAX);

    int e = beg;
    for (; e + 3 < end; e += 4) {
        int s0 = __ldg(&g_ssrc[e]);
        int s1 = __ldg(&g_ssrc[e + 1]);
        int s2 = __ldg(&g_ssrc[e + 2]);
        int s3 = __ldg(&g_ssrc[e + 3]);
        const float4* r0 = (const float4*)(feat + (size_t)s0 * F);
        const float4* r1 = (const float4*)(feat + (size_t)s1 * F);
        const float4* r2 = (const float4*)(feat + (size_t)s2 * F);
        const float4* r3 = (const float4*)(feat + (size_t)s3 * F);
        #pragma unroll
        for (int v = 0; v < VPL; v++) {
            float4 a = __ldg(&r0[v * 32 + lane]);
            float4 b = __ldg(&r1[v * 32 + lane]);
            float4 c = __ldg(&r2[v * 32 + lane]);
            float4 d = __ldg(&r3[v * 32 + lane]);
            acc[v] = f4max(acc[v], f4max(f4max(a, b), f4max(c, d)));
        }
    }
    for (; e < end; e++) {
        int s0 = __ldg(&g_ssrc[e]);
        const float4* r0 = (const float4*)(feat + (size_t)s0 * F);
        #pragma unroll
        for (int v = 0; v < VPL; v++)
            acc[v] = f4max(acc[v], __ldg(&r0[v * 32 + lane]));
    }
    if (beg == end) {
        #pragma unroll
        for (int v = 0; v < VPL; v++)
            acc[v] = make_float4(0.f, 0.f, 0.f, 0.f);
    }
    float4* orow = (float4*)(out + (size_t)warp * F);
    #pragma unroll
    for (int v = 0; v < VPL; v++)
        orow[v * 32 + lane] = acc[v];
}

// ---------------- TF32 tensor-core fused GEMM ------------------------------
// C = relu(A@WA + B@WB + bias). 3xTF32 split for fp32-level accuracy.
// Block 128x128, BK=16, 8 warps (2x4), warp tile 64x32, m16n8k8 mma.

#define GBM 128
#define GBN 128
#define GBK 16
#define ASTR 20
#define WSTR 136

__device__ __forceinline__ unsigned f2tf32(float x) {
    unsigned r;
    asm("cvt.rna.tf32.f32 %0, %1;" : "=r"(r) : "f"(x));
    return r;
}

__device__ __forceinline__ void mma_tf32(float* c, const unsigned* a, const unsigned* b) {
    asm volatile(
        "mma.sync.aligned.m16n8k8.row.col.f32.tf32.tf32.f32 "
        "{%0,%1,%2,%3}, {%4,%5,%6,%7}, {%8,%9}, {%0,%1,%2,%3};"
        : "+f"(c[0]), "+f"(c[1]), "+f"(c[2]), "+f"(c[3])
        : "r"(a[0]), "r"(a[1]), "r"(a[2]), "r"(a[3]), "r"(b[0]), "r"(b[1]));
}

__device__ __forceinline__ void cp16(void* dst, const void* src) {
    unsigned d = (unsigned)__cvta_generic_to_shared(dst);
    asm volatile("cp.async.cg.shared.global [%0], [%1], 16;" :: "r"(d), "l"(src));
}

// Core GEMM body as a device function; callers pick pointers per block.
__device__ __forceinline__ void gemm_body(
    const float* __restrict__ A, const float* __restrict__ WA, int KA,
    const float* __restrict__ B, const float* __restrict__ WB, int KB,
    const float* __restrict__ bias, float* __restrict__ C, int M,
    int brow, int bcol,
    float (*As)[GBM][ASTR], float (*Ws)[GBK][WSTR])
{
    int tid = threadIdx.x, lane = tid & 31, w = tid >> 5;
    int wm = w >> 2, wn = w & 3;

    float acc[4][4][4];
    #pragma unroll
    for (int i = 0; i < 4; i++)
        #pragma unroll
        for (int j = 0; j < 4; j++)
            #pragma unroll
            for (int q = 0; q < 4; q++) acc[i][j][q] = 0.f;

    int itA = KA / GBK, itB = KB / GBK;
    int iters = itA + itB;

    auto load_stage = [&](int it, int buf) {
        int ph = (it >= itA);
        const float* Ap = ph ? B : A;
        const float* Wp = ph ? WB : WA;
        int K = ph ? KB : KA;
        int k0 = (ph ? it - itA : it) * GBK;
        #pragma unroll
        for (int j = 0; j < 2; j++) {
            int id = tid + j * 256;
            int r = id >> 2, c4 = id & 3;
            int rg = brow + r; if (rg > M - 1) rg = M - 1;
            cp16(&As[buf][r][c4 * 4], Ap + (size_t)rg * K + k0 + c4 * 4);
        }
        #pragma unroll
        for (int j = 0; j < 2; j++) {
            int id = tid + j * 256;
            int kr = id >> 5, c4 = id & 31;
            cp16(&Ws[buf][kr][c4 * 4], Wp + (size_t)(k0 + kr) * HID + bcol + c4 * 4);
        }
    };

    load_stage(0, 0);
    asm volatile("cp.async.commit_group;");

    for (int it = 0; it < iters; ++it) {
        int buf = it & 1;
        if (it + 1 < iters) {
            load_stage(it + 1, buf ^ 1);
            asm volatile("cp.async.commit_group;");
            asm volatile("cp.async.wait_group 1;");
        } else {
            asm volatile("cp.async.wait_group 0;");
        }
        __syncthreads();

        #pragma unroll
        for (int ks = 0; ks < GBK / 8; ks++) {
            int kb = ks * 8;
            unsigned bh[4][2], bl[4][2];
            #pragma unroll
            for (int nf = 0; nf < 4; nf++) {
                int nc = wn * 32 + nf * 8 + (lane >> 2);
                float b0 = Ws[buf][kb + (lane & 3)][nc];
                float b1 = Ws[buf][kb + (lane & 3) + 4][nc];
                bh[nf][0] = f2tf32(b0);
                bl[nf][0] = f2tf32(b0 - __uint_as_float(bh[nf][0]));
                bh[nf][1] = f2tf32(b1);
                bl[nf][1] = f2tf32(b1 - __uint_as_float(bh[nf][1]));
            }
            #pragma unroll
            for (int mf = 0; mf < 4; mf++) {
                int mr = wm * 64 + mf * 16 + (lane >> 2);
                float a0 = As[buf][mr][kb + (lane & 3)];
                float a1 = As[buf][mr + 8][kb + (lane & 3)];
                float a2 = As[buf][mr][kb + (lane & 3) + 4];
                float a3 = As[buf][mr + 8][kb + (lane & 3) + 4];
                unsigned ah[4], al[4];
                ah[0] = f2tf32(a0); al[0] = f2tf32(a0 - __uint_as_float(ah[0]));
                ah[1] = f2tf32(a1); al[1] = f2tf32(a1 - __uint_as_float(ah[1]));
                ah[2] = f2tf32(a2); al[2] = f2tf32(a2 - __uint_as_float(ah[2]));
                ah[3] = f2tf32(a3); al[3] = f2tf32(a3 - __uint_as_float(ah[3]));
                #pragma unroll
                for (int nf = 0; nf < 4; nf++) {
                    mma_tf32(acc[mf][nf], ah, bh[nf]);
                    mma_tf32(acc[mf][nf], al, bh[nf]);
                    mma_tf32(acc[mf][nf], ah, bl[nf]);
                }
            }
        }
        __syncthreads();
    }

    #pragma unroll
    for (int mf = 0; mf < 4; mf++) {
        int r0 = brow + wm * 64 + mf * 16 + (lane >> 2);
        #pragma unroll
        for (int nf = 0; nf < 4; nf++) {
            int c0 = bcol + wn * 32 + nf * 8 + (lane & 3) * 2;
            float bx = __ldg(&bias[c0]), by = __ldg(&bias[c0 + 1]);
            if (r0 < M) {
                float2 v = make_float2(fmaxf(acc[mf][nf][0] + bx, 0.f),
                                       fmaxf(acc[mf][nf][1] + by, 0.f));
                *(float2*)(C + (size_t)r0 * HID + c0) = v;
            }
            if (r0 + 8 < M) {
                float2 v = make_float2(fmaxf(acc[mf][nf][2] + bx, 0.f),
                                       fmaxf(acc[mf][nf][3] + by, 0.f));
                *(float2*)(C + (size_t)(r0 + 8) * HID + c0) = v;
            }
        }
    }
}

__global__ __launch_bounds__(256, 2)
void k_gemm_mma(const float* __restrict__ A, const float* __restrict__ WA, int KA,
                const float* __restrict__ B, const float* __restrict__ WB, int KB,
                const float* __restrict__ bias, float* __restrict__ C, int M)
{
    __shared__ float As[2][GBM][ASTR];
    __shared__ float Ws[2][GBK][WSTR];
    gemm_body(A, WA, KA, B, WB, KB, bias, C, M,
              blockIdx.y * GBM, blockIdx.x * GBN, As, Ws);
}

// Dual-branch GEMM for layer 3: grid.x = 4; columns 0-1 -> branch a (rt),
// columns 2-3 -> branch m (mv). Shares A/B tiles in L2, halves tail waste.
__global__ __launch_bounds__(256, 2)
void k_gemm_dual(const float* __restrict__ A, const float* __restrict__ B,
                 const float* __restrict__ Wla, const float* __restrict__ Wra,
                 const float* __restrict__ bla, float* __restrict__ rt,
                 const float* __restrict__ Wlm, const float* __restrict__ Wrm,
                 const float* __restrict__ blm, float* __restrict__ mv,
                 int M)
{
    __shared__ float As[2][GBM][ASTR];
    __shared__ float Ws[2][GBK][WSTR];
    int br = blockIdx.x >> 1;              // 0 = rtang, 1 = movedis
    int bcol = (blockIdx.x & 1) * GBN;
    const float* WA = br ? Wlm : Wla;
    const float* WB = br ? Wrm : Wra;
    const float* bias = br ? blm : bla;
    float* C = br ? mv : rt;
    gemm_body(A, WA, HID, B, WB, HID, bias, C, M,
              blockIdx.y * GBM, bcol, As, Ws);
}

// ---------------- heads ----------------------------------------------------
__global__ void k_heads(const float* __restrict__ Wa, const float* __restrict__ ba,
                        const float* __restrict__ Wm, const float* __restrict__ bm,
                        float* __restrict__ out)
{
    int warp = (blockIdx.x * blockDim.x + threadIdx.x) >> 5;
    int lane = threadIdx.x & 31;
    if (warp >= NNODES) return;
    const float* rrow = g_rt + (size_t)warp * HID;
    const float* mrow = g_mv + (size_t)warp * HID;
    float sa = 0.f, sm = 0.f;
    #pragma unroll
    for (int f = lane; f < HID; f += 32) {
        sa += rrow[f] * __ldg(&Wa[f]);
        sm += mrow[f] * __ldg(&Wm[f]);
    }
    #pragma unroll
    for (int off = 16; off > 0; off >>= 1) {
        sa += __shfl_down_sync(0xffffffffu, sa, off);
        sm += __shfl_down_sync(0xffffffffu, sm, off);
    }
    if (lane == 0) {
        out[warp]          = sa + ba[0];
        out[NNODES + warp] = sm + bm[0];
    }
}

// ---------------- launch ---------------------------------------------------
extern "C" void kernel_launch(void* const* d_in, const int* in_sizes, int n_in,
                              void* d_out, int out_size)
{
    const float* x  = (const float*)d_in[0];
    const void*  ei = d_in[1];
    const float *Wl1 = (const float*)d_in[2],  *bl1 = (const float*)d_in[3],  *Wr1 = (const float*)d_in[4];
    const float *Wl2 = (const float*)d_in[5],  *bl2 = (const float*)d_in[6],  *Wr2 = (const float*)d_in[7];
    const float *Wla = (const float*)d_in[8],  *bla = (const float*)d_in[9],  *Wra = (const float*)d_in[10];
    const float *Wa  = (const float*)d_in[11], *ba  = (const float*)d_in[12];
    const float *Wlm = (const float*)d_in[13], *blm = (const float*)d_in[14], *Wrm = (const float*)d_in[15];
    const float *Wm  = (const float*)d_in[16], *bm  = (const float*)d_in[17];
    float* out = (float*)d_out;

    float *agg, *h1, *h2, *rt, *mv;
    cudaGetSymbolAddress((void**)&agg, g_agg);
    cudaGetSymbolAddress((void**)&h1,  g_h1);
    cudaGetSymbolAddress((void**)&h2,  g_h2);
    cudaGetSymbolAddress((void**)&rt,  g_rt);
    cudaGetSymbolAddress((void**)&mv,  g_mv);

    // CSR build
    k_detect<<<16, 256>>>((const long long*)ei);
    k_hist<<<(NEDGES + 255) / 256, 256>>>(ei);
    k_blockscan<<<SCAN_BLKS, 256>>>();
    k_scanbs<<<1, 256>>>();
    k_applyoff<<<SCAN_BLKS, 256>>>();
    k_scatter<<<(NEDGES + 255) / 256, 256>>>(ei);

    dim3 segGrid((NNODES * 32 + 255) / 256);
    dim3 gemmGrid(HID / GBN, (NNODES + GBM - 1) / GBM);
    dim3 dualGrid(4, (NNODES + GBM - 1) / GBM);

    // layer 1
    k_segmax<FIN><<<segGrid, 256>>>(x, agg);
    k_gemm_mma<<<gemmGrid, 256>>>(agg, Wl1, FIN, x, Wr1, FIN, bl1, h1, NNODES);

    // layer 2
    k_segmax<HID><<<segGrid, 256>>>(h1, agg);
    k_gemm_mma<<<gemmGrid, 256>>>(agg, Wl2, HID, h1, Wr2, HID, bl2, h2, NNODES);

    // layer 3 (shared segmax, dual-branch GEMM)
    k_segmax<HID><<<segGrid, 256>>>(h2, agg);
    k_gemm_dual<<<dualGrid, 256>>>(agg, h2, Wla, Wra, bla, rt,
                                   Wlm, Wrm, blm, mv, NNODES);

    // heads
    k_heads<<<segGrid, 256>>>(Wa, ba, Wm, bm, out);
    (void)in_sizes; (void)n_in; (void)out_size;
}

// round 11
// speedup vs baseline: 2.3868x; 1.3779x over previous
#include <cuda_runtime.h>
#include <cuda_fp16.h>
#include <float.h>

// Problem constants (fixed shapes)
#define NNODES 50000
#define NEDGES 800000
#define FIN    128
#define HID    256
#define SCAN_BLKS ((NNODES + 255) / 256)   // 196

// ---------------- scratch (device globals; no allocation allowed) ----------
__device__ __align__(256) int   g_counts[NNODES];        // zero-init; re-zeroed in k_blockscan
__device__ __align__(256) int   g_rowptr[NNODES + 1];
__device__ __align__(256) int   g_wofs[NNODES];
__device__ __align__(256) int   g_ssrc[NEDGES];
__device__ __align__(256) int   g_bsums[SCAN_BLKS];
__device__ __align__(256) int   g_boff[SCAN_BLKS];
__device__ __align__(256) float g_agg[(size_t)NNODES * HID];
__device__ __align__(256) float g_h1 [(size_t)NNODES * HID];
__device__ __align__(256) float g_h2 [(size_t)NNODES * HID];
__device__ __align__(256) float g_rt [(size_t)NNODES * HID];
__device__ __align__(256) float g_mv [(size_t)NNODES * HID];
__device__ int g_use32 = 0;   // 1 if edge_index is actually int32 in memory

// ---------------- dtype detection -----------------------------------------
__global__ void k_detect(const long long* __restrict__ ei) {
    int i = blockIdx.x * blockDim.x + threadIdx.x;
    if (i < 4096) {
        long long v = ei[i];
        if (v < 0 || v >= NNODES) atomicExch(&g_use32, 1);
    }
}

__device__ __forceinline__ int edge_at(const void* ei, size_t idx) {
    if (g_use32) return ((const int*)ei)[idx];
    return (int)((const long long*)ei)[idx];
}

// ---------------- CSR build ------------------------------------------------
__global__ void k_hist(const void* __restrict__ ei) {
    int i = blockIdx.x * blockDim.x + threadIdx.x;
    if (i < NEDGES) {
        int d = edge_at(ei, (size_t)NEDGES + i);
        if ((unsigned)d < NNODES) atomicAdd(&g_counts[d], 1);
    }
}

// per-block inclusive scan; also re-zeroes counts for the next graph replay
__global__ void k_blockscan() {
    __shared__ int s[256];
    int i = blockIdx.x * 256 + threadIdx.x;
    int v = (i < NNODES) ? g_counts[i] : 0;
    if (i < NNODES) g_counts[i] = 0;
    s[threadIdx.x] = v;
    __syncthreads();
    #pragma unroll
    for (int off = 1; off < 256; off <<= 1) {
        int t = (threadIdx.x >= off) ? s[threadIdx.x - off] : 0;
        __syncthreads();
        s[threadIdx.x] += t;
        __syncthreads();
    }
    if (i < NNODES) g_rowptr[i + 1] = s[threadIdx.x];
    if (threadIdx.x == 255) g_bsums[blockIdx.x] = s[255];
}

// one small block: scan only the 196 block sums
__global__ void k_scanbs() {
    __shared__ int s[256];
    int t = threadIdx.x;
    s[t] = (t < SCAN_BLKS) ? g_bsums[t] : 0;
    __syncthreads();
    #pragma unroll
    for (int off = 1; off < 256; off <<= 1) {
        int v = (t >= off) ? s[t - off] : 0;
        __syncthreads();
        s[t] += v;
        __syncthreads();
    }
    if (t < SCAN_BLKS) g_boff[t] = (t == 0) ? 0 : s[t - 1];
}

// parallel offset apply + wofs emit (196 blocks)
__global__ void k_applyoff() {
    int i = blockIdx.x * 256 + threadIdx.x;
    if (i < NNODES) {
        int v = g_rowptr[i + 1] + g_boff[blockIdx.x];
        g_rowptr[i + 1] = v;
        if (i + 1 < NNODES) g_wofs[i + 1] = v;
    }
    if (i == 0) { g_rowptr[0] = 0; g_wofs[0] = 0; }
}

__global__ void k_scatter(const void* __restrict__ ei) {
    int i = blockIdx.x * blockDim.x + threadIdx.x;
    if (i < NEDGES) {
        int s = edge_at(ei, i);
        int d = edge_at(ei, (size_t)NEDGES + i);
        if ((unsigned)d >= NNODES || (unsigned)s >= NNODES) return;
        int p = atomicAdd(&g_wofs[d], 1);
        if (p < NEDGES) g_ssrc[p] = s;
    }
}

// ---------------- segment max (one warp per node, 4-edge unroll) -----------
__device__ __forceinline__ float4 f4max(float4 a, float4 b) {
    return make_float4(fmaxf(a.x, b.x), fmaxf(a.y, b.y),
                       fmaxf(a.z, b.z), fmaxf(a.w, b.w));
}

template <int F>
__global__ void k_segmax(const float* __restrict__ feat, float* __restrict__ out) {
    constexpr int VPL = F / 128;
    int warp = (blockIdx.x * blockDim.x + threadIdx.x) >> 5;
    int lane = threadIdx.x & 31;
    if (warp >= NNODES) return;
    int beg = __ldg(&g_rowptr[warp]);
    int end = __ldg(&g_rowptr[warp + 1]);

    float4 acc[VPL];
    #pragma unroll
    for (int v = 0; v < VPL; v++)
        acc[v] = make_float4(-FLT_MAX, -FLT_MAX, -FLT_MAX, -FLT_MAX);

    int e = beg;
    for (; e + 3 < end; e += 4) {
        int s0 = __ldg(&g_ssrc[e]);
        int s1 = __ldg(&g_ssrc[e + 1]);
        int s2 = __ldg(&g_ssrc[e + 2]);
        int s3 = __ldg(&g_ssrc[e + 3]);
        const float4* r0 = (const float4*)(feat + (size_t)s0 * F);
        const float4* r1 = (const float4*)(feat + (size_t)s1 * F);
        const float4* r2 = (const float4*)(feat + (size_t)s2 * F);
        const float4* r3 = (const float4*)(feat + (size_t)s3 * F);
        #pragma unroll
        for (int v = 0; v < VPL; v++) {
            float4 a = __ldg(&r0[v * 32 + lane]);
            float4 b = __ldg(&r1[v * 32 + lane]);
            float4 c = __ldg(&r2[v * 32 + lane]);
            float4 d = __ldg(&r3[v * 32 + lane]);
            acc[v] = f4max(acc[v], f4max(f4max(a, b), f4max(c, d)));
        }
    }
    for (; e < end; e++) {
        int s0 = __ldg(&g_ssrc[e]);
        const float4* r0 = (const float4*)(feat + (size_t)s0 * F);
        #pragma unroll
        for (int v = 0; v < VPL; v++)
            acc[v] = f4max(acc[v], __ldg(&r0[v * 32 + lane]));
    }
    if (beg == end) {
        #pragma unroll
        for (int v = 0; v < VPL; v++)
            acc[v] = make_float4(0.f, 0.f, 0.f, 0.f);
    }
    float4* orow = (float4*)(out + (size_t)warp * F);
    #pragma unroll
    for (int v = 0; v < VPL; v++)
        orow[v * 32 + lane] = acc[v];
}

// ---------------- FP16x3 tensor-core fused GEMM ----------------------------
// C = relu(A@WA + B@WB + bias). fp16 hi/lo split (11-bit mantissa like TF32):
// ah*bh + al*bh + ah*bl -> residual ~2^-22, same accuracy as 3xTF32, but
// m16n8k16 gives 2x K per mma instruction.
// Block 128x128, BK=16, 8 warps (2x4), warp tile 64x32.

#define GBM 128
#define GBN 128
#define GBK 16
#define ASTR 20      // As row stride (floats); float2 frag loads, minor conflicts
#define WSTR 132     // Ws row stride: 2*132*t mod 32 = {0,8,16,24} -> conflict-free

__device__ __forceinline__ void mma_f16(float* c, const unsigned* a, const unsigned* b) {
    asm volatile(
        "mma.sync.aligned.m16n8k16.row.col.f32.f16.f16.f32 "
        "{%0,%1,%2,%3}, {%4,%5,%6,%7}, {%8,%9}, {%0,%1,%2,%3};"
        : "+f"(c[0]), "+f"(c[1]), "+f"(c[2]), "+f"(c[3])
        : "r"(a[0]), "r"(a[1]), "r"(a[2]), "r"(a[3]), "r"(b[0]), "r"(b[1]));
}

// split (x,y) into packed-half2 hi and lo parts (lo = round(v - float(hi)))
__device__ __forceinline__ void split2(float x, float y, unsigned& h, unsigned& l) {
    __half2 H = __floats2half2_rn(x, y);
    float2 R = __half22float2(H);
    __half2 L = __floats2half2_rn(x - R.x, y - R.y);
    h = *reinterpret_cast<unsigned*>(&H);
    l = *reinterpret_cast<unsigned*>(&L);
}

__device__ __forceinline__ void cp16(void* dst, const void* src) {
    unsigned d = (unsigned)__cvta_generic_to_shared(dst);
    asm volatile("cp.async.cg.shared.global [%0], [%1], 16;" :: "r"(d), "l"(src));
}

// Core GEMM body as a device function; callers pick pointers per block.
__device__ __forceinline__ void gemm_body(
    const float* __restrict__ A, const float* __restrict__ WA, int KA,
    const float* __restrict__ B, const float* __restrict__ WB, int KB,
    const float* __restrict__ bias, float* __restrict__ C, int M,
    int brow, int bcol,
    float (*As)[GBM][ASTR], float (*Ws)[GBK][WSTR])
{
    int tid = threadIdx.x, lane = tid & 31, w = tid >> 5;
    int wm = w >> 2, wn = w & 3;
    int grp = lane >> 2;            // 0..7
    int qk  = (lane & 3) * 2;       // 0,2,4,6

    float acc[4][4][4];
    #pragma unroll
    for (int i = 0; i < 4; i++)
        #pragma unroll
        for (int j = 0; j < 4; j++)
            #pragma unroll
            for (int q = 0; q < 4; q++) acc[i][j][q] = 0.f;

    int itA = KA / GBK, itB = KB / GBK;
    int iters = itA + itB;

    auto load_stage = [&](int it, int buf) {
        int ph = (it >= itA);
        const float* Ap = ph ? B : A;
        const float* Wp = ph ? WB : WA;
        int K = ph ? KB : KA;
        int k0 = (ph ? it - itA : it) * GBK;
        #pragma unroll
        for (int j = 0; j < 2; j++) {
            int id = tid + j * 256;
            int r = id >> 2, c4 = id & 3;
            int rg = brow + r; if (rg > M - 1) rg = M - 1;
            cp16(&As[buf][r][c4 * 4], Ap + (size_t)rg * K + k0 + c4 * 4);
        }
        #pragma unroll
        for (int j = 0; j < 2; j++) {
            int id = tid + j * 256;
            int kr = id >> 5, c4 = id & 31;
            cp16(&Ws[buf][kr][c4 * 4], Wp + (size_t)(k0 + kr) * HID + bcol + c4 * 4);
        }
    };

    load_stage(0, 0);
    asm volatile("cp.async.commit_group;");

    for (int it = 0; it < iters; ++it) {
        int buf = it & 1;
        if (it + 1 < iters) {
            load_stage(it + 1, buf ^ 1);
            asm volatile("cp.async.commit_group;");
            asm volatile("cp.async.wait_group 1;");
        } else {
            asm volatile("cp.async.wait_group 0;");
        }
        __syncthreads();

        // one m16n8k16 k-step covers the whole BK=16 tile
        unsigned bh[4][2], bl[4][2];
        #pragma unroll
        for (int nf = 0; nf < 4; nf++) {
            int nc = wn * 32 + nf * 8 + grp;
            float f0 = Ws[buf][qk][nc];
            float f1 = Ws[buf][qk + 1][nc];
            float f2 = Ws[buf][qk + 8][nc];
            float f3 = Ws[buf][qk + 9][nc];
            split2(f0, f1, bh[nf][0], bl[nf][0]);
            split2(f2, f3, bh[nf][1], bl[nf][1]);
        }
        #pragma unroll
        for (int mf = 0; mf < 4; mf++) {
            int mr = wm * 64 + mf * 16 + grp;
            float2 p0 = *(const float2*)&As[buf][mr][qk];
            float2 p1 = *(const float2*)&As[buf][mr + 8][qk];
            float2 p2 = *(const float2*)&As[buf][mr][qk + 8];
            float2 p3 = *(const float2*)&As[buf][mr + 8][qk + 8];
            unsigned ah[4], al[4];
            split2(p0.x, p0.y, ah[0], al[0]);
            split2(p1.x, p1.y, ah[1], al[1]);
            split2(p2.x, p2.y, ah[2], al[2]);
            split2(p3.x, p3.y, ah[3], al[3]);
            #pragma unroll
            for (int nf = 0; nf < 4; nf++) {
                mma_f16(acc[mf][nf], ah, bh[nf]);
                mma_f16(acc[mf][nf], al, bh[nf]);
                mma_f16(acc[mf][nf], ah, bl[nf]);
            }
        }
        __syncthreads();
    }

    #pragma unroll
    for (int mf = 0; mf < 4; mf++) {
        int r0 = brow + wm * 64 + mf * 16 + grp;
        #pragma unroll
        for (int nf = 0; nf < 4; nf++) {
            int c0 = bcol + wn * 32 + nf * 8 + (lane & 3) * 2;
            float bx = __ldg(&bias[c0]), by = __ldg(&bias[c0 + 1]);
            if (r0 < M) {
                float2 v = make_float2(fmaxf(acc[mf][nf][0] + bx, 0.f),
                                       fmaxf(acc[mf][nf][1] + by, 0.f));
                *(float2*)(C + (size_t)r0 * HID + c0) = v;
            }
            if (r0 + 8 < M) {
                float2 v = make_float2(fmaxf(acc[mf][nf][2] + bx, 0.f),
                                       fmaxf(acc[mf][nf][3] + by, 0.f));
                *(float2*)(C + (size_t)(r0 + 8) * HID + c0) = v;
            }
        }
    }
}

__global__ __launch_bounds__(256, 2)
void k_gemm_mma(const float* __restrict__ A, const float* __restrict__ WA, int KA,
                const float* __restrict__ B, const float* __restrict__ WB, int KB,
                const float* __restrict__ bias, float* __restrict__ C, int M)
{
    __shared__ float As[2][GBM][ASTR];
    __shared__ float Ws[2][GBK][WSTR];
    gemm_body(A, WA, KA, B, WB, KB, bias, C, M,
              blockIdx.y * GBM, blockIdx.x * GBN, As, Ws);
}

// Dual-branch GEMM for layer 3: grid.x = 4; columns 0-1 -> branch a (rt),
// columns 2-3 -> branch m (mv). Shares A/B tiles in L2, halves tail waste.
__global__ __launch_bounds__(256, 2)
void k_gemm_dual(const float* __restrict__ A, const float* __restrict__ B,
                 const float* __restrict__ Wla, const float* __restrict__ Wra,
                 const float* __restrict__ bla, float* __restrict__ rt,
                 const float* __restrict__ Wlm, const float* __restrict__ Wrm,
                 const float* __restrict__ blm, float* __restrict__ mv,
                 int M)
{
    __shared__ float As[2][GBM][ASTR];
    __shared__ float Ws[2][GBK][WSTR];
    int br = blockIdx.x >> 1;              // 0 = rtang, 1 = movedis
    int bcol = (blockIdx.x & 1) * GBN;
    const float* WA = br ? Wlm : Wla;
    const float* WB = br ? Wrm : Wra;
    const float* bias = br ? blm : bla;
    float* C = br ? mv : rt;
    gemm_body(A, WA, HID, B, WB, HID, bias, C, M,
              blockIdx.y * GBM, bcol, As, Ws);
}

// ---------------- heads ----------------------------------------------------
__global__ void k_heads(const float* __restrict__ Wa, const float* __restrict__ ba,
                        const float* __restrict__ Wm, const float* __restrict__ bm,
                        float* __restrict__ out)
{
    int warp = (blockIdx.x * blockDim.x + threadIdx.x) >> 5;
    int lane = threadIdx.x & 31;
    if (warp >= NNODES) return;
    const float* rrow = g_rt + (size_t)warp * HID;
    const float* mrow = g_mv + (size_t)warp * HID;
    float sa = 0.f, sm = 0.f;
    #pragma unroll
    for (int f = lane; f < HID; f += 32) {
        sa += rrow[f] * __ldg(&Wa[f]);
        sm += mrow[f] * __ldg(&Wm[f]);
    }
    #pragma unroll
    for (int off = 16; off > 0; off >>= 1) {
        sa += __shfl_down_sync(0xffffffffu, sa, off);
        sm += __shfl_down_sync(0xffffffffu, sm, off);
    }
    if (lane == 0) {
        out[warp]          = sa + ba[0];
        out[NNODES + warp] = sm + bm[0];
    }
}

// ---------------- launch ---------------------------------------------------
extern "C" void kernel_launch(void* const* d_in, const int* in_sizes, int n_in,
                              void* d_out, int out_size)
{
    const float* x  = (const float*)d_in[0];
    const void*  ei = d_in[1];
    const float *Wl1 = (const float*)d_in[2],  *bl1 = (const float*)d_in[3],  *Wr1 = (const float*)d_in[4];
    const float *Wl2 = (const float*)d_in[5],  *bl2 = (const float*)d_in[6],  *Wr2 = (const float*)d_in[7];
    const float *Wla = (const float*)d_in[8],  *bla = (const float*)d_in[9],  *Wra = (const float*)d_in[10];
    const float *Wa  = (const float*)d_in[11], *ba  = (const float*)d_in[12];
    const float *Wlm = (const float*)d_in[13], *blm = (const float*)d_in[14], *Wrm = (const float*)d_in[15];
    const float *Wm  = (const float*)d_in[16], *bm  = (const float*)d_in[17];
    float* out = (float*)d_out;

    float *agg, *h1, *h2, *rt, *mv;
    cudaGetSymbolAddress((void**)&agg, g_agg);
    cudaGetSymbolAddress((void**)&h1,  g_h1);
    cudaGetSymbolAddress((void**)&h2,  g_h2);
    cudaGetSymbolAddress((void**)&rt,  g_rt);
    cudaGetSymbolAddress((void**)&mv,  g_mv);

    // CSR build
    k_detect<<<16, 256>>>((const long long*)ei);
    k_hist<<<(NEDGES + 255) / 256, 256>>>(ei);
    k_blockscan<<<SCAN_BLKS, 256>>>();
    k_scanbs<<<1, 256>>>();
    k_applyoff<<<SCAN_BLKS, 256>>>();
    k_scatter<<<(NEDGES + 255) / 256, 256>>>(ei);

    dim3 segGrid((NNODES * 32 + 255) / 256);
    dim3 gemmGrid(HID / GBN, (NNODES + GBM - 1) / GBM);
    dim3 dualGrid(4, (NNODES + GBM - 1) / GBM);

    // layer 1
    k_segmax<FIN><<<segGrid, 256>>>(x, agg);
    k_gemm_mma<<<gemmGrid, 256>>>(agg, Wl1, FIN, x, Wr1, FIN, bl1, h1, NNODES);

    // layer 2
    k_segmax<HID><<<segGrid, 256>>>(h1, agg);
    k_gemm_mma<<<gemmGrid, 256>>>(agg, Wl2, HID, h1, Wr2, HID, bl2, h2, NNODES);

    // layer 3 (shared segmax, dual-branch GEMM)
    k_segmax<HID><<<segGrid, 256>>>(h2, agg);
    k_gemm_dual<<<dualGrid, 256>>>(agg, h2, Wla, Wra, bla, rt,
                                   Wlm, Wrm, blm, mv, NNODES);

    // heads
    k_heads<<<segGrid, 256>>>(Wa, ba, Wm, bm, out);
    (void)in_sizes; (void)n_in; (void)out_size;
}

// round 14
// speedup vs baseline: 2.5452x; 1.0664x over previous
#include <cuda_runtime.h>
#include <cuda_fp16.h>
#include <float.h>

// Problem constants (fixed shapes)
#define NNODES 50000
#define NEDGES 800000
#define FIN    128
#define HID    256
#define SCAN_BLKS ((NNODES + 255) / 256)   // 196

// weight pack offsets (u32 units): Wl1,Wr1 are 128x256; rest 256x256
#define WOFF0 0          // Wl1
#define WOFF1 16384      // Wr1
#define WOFF2 32768      // Wl2
#define WOFF3 65536      // Wr2
#define WOFF4 98304      // Wla
#define WOFF5 131072     // Wra
#define WOFF6 163840     // Wlm
#define WOFF7 196608     // Wrm
#define WTOT  229376

// ---------------- scratch (device globals; no allocation allowed) ----------
__device__ __align__(256) int   g_counts[NNODES];
__device__ __align__(256) int   g_rowptr[NNODES + 1];
__device__ __align__(256) int   g_wofs[NNODES];
__device__ __align__(256) int   g_ssrc[NEDGES];
__device__ __align__(256) int   g_bsums[SCAN_BLKS];
__device__ __align__(256) int   g_boff[SCAN_BLKS];
__device__ __align__(256) float g_h1 [(size_t)NNODES * HID];
__device__ __align__(256) float g_h2 [(size_t)NNODES * HID];
__device__ __align__(256) float g_rt [(size_t)NNODES * HID];
__device__ __align__(256) float g_mv [(size_t)NNODES * HID];
// packed half2 (hi/lo split) operand buffers
__device__ __align__(256) unsigned g_xh [(size_t)NNODES * (FIN/2)];
__device__ __align__(256) unsigned g_xl [(size_t)NNODES * (FIN/2)];
__device__ __align__(256) unsigned g_aggh[(size_t)NNODES * (HID/2)];
__device__ __align__(256) unsigned g_aggl[(size_t)NNODES * (HID/2)];
__device__ __align__(256) unsigned g_h1h[(size_t)NNODES * (HID/2)];
__device__ __align__(256) unsigned g_h1l[(size_t)NNODES * (HID/2)];
__device__ __align__(256) unsigned g_h2h[(size_t)NNODES * (HID/2)];
__device__ __align__(256) unsigned g_h2l[(size_t)NNODES * (HID/2)];
__device__ __align__(256) unsigned g_wh [WTOT];
__device__ __align__(256) unsigned g_wl [WTOT];
__device__ int g_use32 = 0;

// ---------------- helpers --------------------------------------------------
__device__ __forceinline__ void split2(float x, float y, unsigned& h, unsigned& l) {
    __half2 H = __floats2half2_rn(x, y);
    float2 R = __half22float2(H);
    __half2 L = __floats2half2_rn(x - R.x, y - R.y);
    h = *reinterpret_cast<unsigned*>(&H);
    l = *reinterpret_cast<unsigned*>(&L);
}

// ---------------- dtype detection -----------------------------------------
__global__ void k_detect(const long long* __restrict__ ei) {
    int i = blockIdx.x * blockDim.x + threadIdx.x;
    if (i < 4096) {
        long long v = ei[i];
        if (v < 0 || v >= NNODES) atomicExch(&g_use32, 1);
    }
}

__device__ __forceinline__ int edge_at(const void* ei, size_t idx) {
    if (g_use32) return ((const int*)ei)[idx];
    return (int)((const long long*)ei)[idx];
}

// ---------------- CSR build ------------------------------------------------
__global__ void k_hist(const void* __restrict__ ei) {
    int i = blockIdx.x * blockDim.x + threadIdx.x;
    if (i < NEDGES) {
        int d = edge_at(ei, (size_t)NEDGES + i);
        if ((unsigned)d < NNODES) atomicAdd(&g_counts[d], 1);
    }
}

__global__ void k_blockscan() {
    __shared__ int s[256];
    int i = blockIdx.x * 256 + threadIdx.x;
    int v = (i < NNODES) ? g_counts[i] : 0;
    if (i < NNODES) g_counts[i] = 0;
    s[threadIdx.x] = v;
    __syncthreads();
    #pragma unroll
    for (int off = 1; off < 256; off <<= 1) {
        int t = (threadIdx.x >= off) ? s[threadIdx.x - off] : 0;
        __syncthreads();
        s[threadIdx.x] += t;
        __syncthreads();
    }
    if (i < NNODES) g_rowptr[i + 1] = s[threadIdx.x];
    if (threadIdx.x == 255) g_bsums[blockIdx.x] = s[255];
}

__global__ void k_scanbs() {
    __shared__ int s[256];
    int t = threadIdx.x;
    s[t] = (t < SCAN_BLKS) ? g_bsums[t] : 0;
    __syncthreads();
    #pragma unroll
    for (int off = 1; off < 256; off <<= 1) {
        int v = (t >= off) ? s[t - off] : 0;
        __syncthreads();
        s[t] += v;
        __syncthreads();
    }
    if (t < SCAN_BLKS) g_boff[t] = (t == 0) ? 0 : s[t - 1];
}

__global__ void k_applyoff() {
    int i = blockIdx.x * 256 + threadIdx.x;
    if (i < NNODES) {
        int v = g_rowptr[i + 1] + g_boff[blockIdx.x];
        g_rowptr[i + 1] = v;
        if (i + 1 < NNODES) g_wofs[i + 1] = v;
    }
    if (i == 0) { g_rowptr[0] = 0; g_wofs[0] = 0; }
}

__global__ void k_scatter(const void* __restrict__ ei) {
    int i = blockIdx.x * blockDim.x + threadIdx.x;
    if (i < NEDGES) {
        int s = edge_at(ei, i);
        int d = edge_at(ei, (size_t)NEDGES + i);
        if ((unsigned)d >= NNODES || (unsigned)s >= NNODES) return;
        int p = atomicAdd(&g_wofs[d], 1);
        if (p < NEDGES) g_ssrc[p] = s;
    }
}

// ---------------- operand pre-packing --------------------------------------
// x -> packed hi/lo half2 [M][FIN/2]
__global__ void k_cvt_x(const float* __restrict__ x) {
    int i = blockIdx.x * blockDim.x + threadIdx.x;   // u32 index
    if (i < NNODES * (FIN / 2)) {
        float2 v = *(const float2*)(x + (size_t)i * 2);
        unsigned h, l;
        split2(v.x, v.y, h, l);
        g_xh[i] = h; g_xl[i] = l;
    }
}

// all 8 weight matrices -> packed [K/2][N] u32 (k-pairs; n unpacked)
__global__ void k_cvt_w(const float* __restrict__ Wl1, const float* __restrict__ Wr1,
                        const float* __restrict__ Wl2, const float* __restrict__ Wr2,
                        const float* __restrict__ Wla, const float* __restrict__ Wra,
                        const float* __restrict__ Wlm, const float* __restrict__ Wrm)
{
    int i = blockIdx.x * blockDim.x + threadIdx.x;
    if (i >= WTOT) return;
    const float* src; int base;
    if      (i < WOFF1) { src = Wl1; base = WOFF0; }
    else if (i < WOFF2) { src = Wr1; base = WOFF1; }
    else if (i < WOFF3) { src = Wl2; base = WOFF2; }
    else if (i < WOFF4) { src = Wr2; base = WOFF3; }
    else if (i < WOFF5) { src = Wla; base = WOFF4; }
    else if (i < WOFF6) { src = Wra; base = WOFF5; }
    else if (i < WOFF7) { src = Wlm; base = WOFF6; }
    else                { src = Wrm; base = WOFF7; }
    int idx = i - base;
    int kk = idx >> 8;          // k-pair row
    int n  = idx & 255;         // n column (float == u32 index)
    float a = src[(size_t)(2 * kk) * HID + n];
    float b = src[(size_t)(2 * kk + 1) * HID + n];
    unsigned h, l;
    split2(a, b, h, l);
    g_wh[i] = h; g_wl[i] = l;
}

// ---------------- segment max: fp32 gather, packed hi/lo emit --------------
__device__ __forceinline__ float4 f4max(float4 a, float4 b) {
    return make_float4(fmaxf(a.x, b.x), fmaxf(a.y, b.y),
                       fmaxf(a.z, b.z), fmaxf(a.w, b.w));
}

template <int F>
__global__ void k_segmax(const float* __restrict__ feat,
                         unsigned* __restrict__ outh, unsigned* __restrict__ outl) {
    constexpr int VPL = F / 128;
    int warp = (blockIdx.x * blockDim.x + threadIdx.x) >> 5;
    int lane = threadIdx.x & 31;
    if (warp >= NNODES) return;
    int beg = __ldg(&g_rowptr[warp]);
    int end = __ldg(&g_rowptr[warp + 1]);

    float4 acc[VPL];
    #pragma unroll
    for (int v = 0; v < VPL; v++)
        acc[v] = make_float4(-FLT_MAX, -FLT_MAX, -FLT_MAX, -FLT_MAX);

    int e = beg;
    for (; e + 3 < end; e += 4) {
        int s0 = __ldg(&g_ssrc[e]);
        int s1 = __ldg(&g_ssrc[e + 1]);
        int s2 = __ldg(&g_ssrc[e + 2]);
        int s3 = __ldg(&g_ssrc[e + 3]);
        const float4* r0 = (const float4*)(feat + (size_t)s0 * F);
        const float4* r1 = (const float4*)(feat + (size_t)s1 * F);
        const float4* r2 = (const float4*)(feat + (size_t)s2 * F);
        const float4* r3 = (const float4*)(feat + (size_t)s3 * F);
        #pragma unroll
        for (int v = 0; v < VPL; v++) {
            float4 a = __ldg(&r0[v * 32 + lane]);
            float4 b = __ldg(&r1[v * 32 + lane]);
            float4 c = __ldg(&r2[v * 32 + lane]);
            float4 d = __ldg(&r3[v * 32 + lane]);
            acc[v] = f4max(acc[v], f4max(f4max(a, b), f4max(c, d)));
        }
    }
    for (; e < end; e++) {
        int s0 = __ldg(&g_ssrc[e]);
        const float4* r0 = (const float4*)(feat + (size_t)s0 * F);
        #pragma unroll
        for (int v = 0; v < VPL; v++)
            acc[v] = f4max(acc[v], __ldg(&r0[v * 32 + lane]));
    }
    if (beg == end) {
        #pragma unroll
        for (int v = 0; v < VPL; v++)
            acc[v] = make_float4(0.f, 0.f, 0.f, 0.f);
    }
    // emit packed hi/lo half2 pairs: row stride F/2 u32
    #pragma unroll
    for (int v = 0; v < VPL; v++) {
        unsigned h0, l0, h1, l1;
        split2(acc[v].x, acc[v].y, h0, l0);
        split2(acc[v].z, acc[v].w, h1, l1);
        size_t idx = (size_t)warp * (F / 2) + (v * 32 + lane) * 2;
        *(uint2*)(outh + idx) = make_uint2(h0, h1);
        *(uint2*)(outl + idx) = make_uint2(l0, l1);
    }
}

// ---------------- pure-HMMA FP16x3 fused GEMM ------------------------------
// C = relu(A@WA + B@WB + bias), all operands pre-split into half2-packed
// hi/lo arrays: A,B as [M][K/2] u32 (k-pairs), W as [K/2][N] u32 (n unpacked).
// Block 128x128, BK=16, 8 warps (2x4), warp tile 64x32, m16n8k16.

#define GBM 128
#define GBN 128
#define SA_STR 12    // u32 row stride for A tiles (8 data + 4 pad)
#define SW_STR 136   // u32 row stride for W tiles (128 data + 8 pad)

__device__ __forceinline__ void mma_f16(float* c, const unsigned* a, const unsigned* b) {
    asm volatile(
        "mma.sync.aligned.m16n8k16.row.col.f32.f16.f16.f32 "
        "{%0,%1,%2,%3}, {%4,%5,%6,%7}, {%8,%9}, {%0,%1,%2,%3};"
        : "+f"(c[0]), "+f"(c[1]), "+f"(c[2]), "+f"(c[3])
        : "r"(a[0]), "r"(a[1]), "r"(a[2]), "r"(a[3]), "r"(b[0]), "r"(b[1]));
}

__device__ __forceinline__ void cp16(void* dst, const void* src) {
    unsigned d = (unsigned)__cvta_generic_to_shared(dst);
    asm volatile("cp.async.cg.shared.global [%0], [%1], 16;" :: "r"(d), "l"(src));
}

struct __align__(16) GemmSmem {
    unsigned Ah[2][GBM][SA_STR];
    unsigned Al[2][GBM][SA_STR];
    unsigned Wh[2][8][SW_STR];
    unsigned Wl[2][8][SW_STR];
};

// ncol0: block's base n column (float units == W u32 units), 0 or 128.
__device__ __forceinline__ void gemm_body(
    const unsigned* __restrict__ Ah, const unsigned* __restrict__ Al, int KA,
    const unsigned* __restrict__ Bh, const unsigned* __restrict__ Bl, int KB,
    const unsigned* __restrict__ WAh, const unsigned* __restrict__ WAl,
    const unsigned* __restrict__ WBh, const unsigned* __restrict__ WBl,
    const float* __restrict__ bias, float* __restrict__ C,
    unsigned* __restrict__ Ph, unsigned* __restrict__ Pl,   // packed C out (may be null)
    int M, int brow, int ncol0, GemmSmem* S)
{
    int tid = threadIdx.x, lane = tid & 31, w = tid >> 5;
    int wm = w >> 2, wn = w & 3;
    int grp = lane >> 2;            // 0..7
    int kk4 = lane & 3;             // 0..3

    float acc[4][4][4];
    #pragma unroll
    for (int i = 0; i < 4; i++)
        #pragma unroll
        for (int j = 0; j < 4; j++)
            #pragma unroll
            for (int q = 0; q < 4; q++) acc[i][j][q] = 0.f;

    int itA = KA / 16, itB = KB / 16;
    int iters = itA + itB;
    int KAu = KA / 2, KBu = KB / 2;

    auto load_stage = [&](int it, int buf) {
        int ph = (it >= itA);
        const unsigned* Ap_h = ph ? Bh : Ah;
        const unsigned* Ap_l = ph ? Bl : Al;
        const unsigned* Wp_h = ph ? WBh : WAh;
        const unsigned* Wp_l = ph ? WBl : WAl;
        int Ku = ph ? KBu : KAu;
        int kk0 = (ph ? it - itA : it) * 8;   // u32 / k-pair offset
        // A tile: 128 rows x 8 u32 (hi and lo)
        {
            int r = tid >> 1, half = tid & 1;
            int rg = brow + r; if (rg > M - 1) rg = M - 1;
            size_t so = (size_t)rg * Ku + kk0 + half * 4;
            cp16(&S->Ah[buf][r][half * 4], Ap_h + so);
            cp16(&S->Al[buf][r][half * 4], Ap_l + so);
        }
        // W tile: 8 k-pair rows x 128 n-cols u32 (hi and lo)
        {
            int kr = tid >> 5, c4 = tid & 31;
            size_t so = (size_t)(kk0 + kr) * HID + ncol0 + c4 * 4;
            cp16(&S->Wh[buf][kr][c4 * 4], Wp_h + so);
            cp16(&S->Wl[buf][kr][c4 * 4], Wp_l + so);
        }
    };

    load_stage(0, 0);
    asm volatile("cp.async.commit_group;");

    for (int it = 0; it < iters; ++it) {
        int buf = it & 1;
        if (it + 1 < iters) {
            load_stage(it + 1, buf ^ 1);
            asm volatile("cp.async.commit_group;");
            asm volatile("cp.async.wait_group 1;");
        } else {
            asm volatile("cp.async.wait_group 0;");
        }
        __syncthreads();

        unsigned bh[4][2], bl[4][2];
        #pragma unroll
        for (int nf = 0; nf < 4; nf++) {
            int nc = wn * 32 + nf * 8 + grp;
            bh[nf][0] = S->Wh[buf][kk4][nc];
            bh[nf][1] = S->Wh[buf][kk4 + 4][nc];
            bl[nf][0] = S->Wl[buf][kk4][nc];
            bl[nf][1] = S->Wl[buf][kk4 + 4][nc];
        }
        #pragma unroll
        for (int mf = 0; mf < 4; mf++) {
            int mr = wm * 64 + mf * 16 + grp;
            unsigned ah[4], al[4];
            ah[0] = S->Ah[buf][mr][kk4];
            ah[1] = S->Ah[buf][mr + 8][kk4];
            ah[2] = S->Ah[buf][mr][kk4 + 4];
            ah[3] = S->Ah[buf][mr + 8][kk4 + 4];
            al[0] = S->Al[buf][mr][kk4];
            al[1] = S->Al[buf][mr + 8][kk4];
            al[2] = S->Al[buf][mr][kk4 + 4];
            al[3] = S->Al[buf][mr + 8][kk4 + 4];
            #pragma unroll
            for (int nf = 0; nf < 4; nf++) {
                mma_f16(acc[mf][nf], ah, bh[nf]);
                mma_f16(acc[mf][nf], al, bh[nf]);
                mma_f16(acc[mf][nf], ah, bl[nf]);
            }
        }
        __syncthreads();
    }

    #pragma unroll
    for (int mf = 0; mf < 4; mf++) {
        int r0 = brow + wm * 64 + mf * 16 + grp;
        #pragma unroll
        for (int nf = 0; nf < 4; nf++) {
            int c0 = ncol0 + wn * 32 + nf * 8 + (lane & 3) * 2;  // float col
            float bx = __ldg(&bias[c0]), by = __ldg(&bias[c0 + 1]);
            if (r0 < M) {
                float vx = fmaxf(acc[mf][nf][0] + bx, 0.f);
                float vy = fmaxf(acc[mf][nf][1] + by, 0.f);
                *(float2*)(C + (size_t)r0 * HID + c0) = make_float2(vx, vy);
                if (Ph) {
                    unsigned h, l; split2(vx, vy, h, l);
                    size_t pi = (size_t)r0 * (HID / 2) + c0 / 2;
                    Ph[pi] = h; Pl[pi] = l;
                }
            }
            if (r0 + 8 < M) {
                float vx = fmaxf(acc[mf][nf][2] + bx, 0.f);
                float vy = fmaxf(acc[mf][nf][3] + by, 0.f);
                *(float2*)(C + (size_t)(r0 + 8) * HID + c0) = make_float2(vx, vy);
                if (Ph) {
                    unsigned h, l; split2(vx, vy, h, l);
                    size_t pi = (size_t)(r0 + 8) * (HID / 2) + c0 / 2;
                    Ph[pi] = h; Pl[pi] = l;
                }
            }
        }
    }
}

__global__ __launch_bounds__(256, 2)
void k_gemm_mma(const unsigned* __restrict__ Ah, const unsigned* __restrict__ Al, int KA,
                const unsigned* __restrict__ Bh, const unsigned* __restrict__ Bl, int KB,
                int woffA, int woffB,
                const float* __restrict__ bias, float* __restrict__ C,
                unsigned* __restrict__ Ph, unsigned* __restrict__ Pl, int M)
{
    __shared__ GemmSmem S;
    gemm_body(Ah, Al, KA, Bh, Bl, KB,
              g_wh + woffA, g_wl + woffA, g_wh + woffB, g_wl + woffB,
              bias, C, Ph, Pl, M,
              blockIdx.y * GBM, blockIdx.x * GBN, &S);
}

// Dual-branch GEMM for layer 3: grid.x = 4; cols 0-1 -> rt branch, 2-3 -> mv.
__global__ __launch_bounds__(256, 2)
void k_gemm_dual(const unsigned* __restrict__ Ah, const unsigned* __restrict__ Al,
                 const unsigned* __restrict__ Bh, const unsigned* __restrict__ Bl,
                 const float* __restrict__ bla, float* __restrict__ rt,
                 const float* __restrict__ blm, float* __restrict__ mv, int M)
{
    __shared__ GemmSmem S;
    int br = blockIdx.x >> 1;
    int ncol0 = (blockIdx.x & 1) * GBN;
    int woffA = br ? WOFF6 : WOFF4;
    int woffB = br ? WOFF7 : WOFF5;
    const float* bias = br ? blm : bla;
    float* C = br ? mv : rt;
    gemm_body(Ah, Al, HID, Bh, Bl, HID,
              g_wh + woffA, g_wl + woffA, g_wh + woffB, g_wl + woffB,
              bias, C, (unsigned*)0, (unsigned*)0, M,
              blockIdx.y * GBM, ncol0, &S);
}

// ---------------- heads ----------------------------------------------------
__global__ void k_heads(const float* __restrict__ Wa, const float* __restrict__ ba,
                        const float* __restrict__ Wm, const float* __restrict__ bm,
                        float* __restrict__ out)
{
    int warp = (blockIdx.x * blockDim.x + threadIdx.x) >> 5;
    int lane = threadIdx.x & 31;
    if (warp >= NNODES) return;
    const float* rrow = g_rt + (size_t)warp * HID;
    const float* mrow = g_mv + (size_t)warp * HID;
    float sa = 0.f, sm = 0.f;
    #pragma unroll
    for (int f = lane; f < HID; f += 32) {
        sa += rrow[f] * __ldg(&Wa[f]);
        sm += mrow[f] * __ldg(&Wm[f]);
    }
    #pragma unroll
    for (int off = 16; off > 0; off >>= 1) {
        sa += __shfl_down_sync(0xffffffffu, sa, off);
        sm += __shfl_down_sync(0xffffffffu, sm, off);
    }
    if (lane == 0) {
        out[warp]          = sa + ba[0];
        out[NNODES + warp] = sm + bm[0];
    }
}

// ---------------- launch ---------------------------------------------------
extern "C" void kernel_launch(void* const* d_in, const int* in_sizes, int n_in,
                              void* d_out, int out_size)
{
    const float* x  = (const float*)d_in[0];
    const void*  ei = d_in[1];
    const float *Wl1 = (const float*)d_in[2],  *bl1 = (const float*)d_in[3],  *Wr1 = (const float*)d_in[4];
    const float *Wl2 = (const float*)d_in[5],  *bl2 = (const float*)d_in[6],  *Wr2 = (const float*)d_in[7];
    const float *Wla = (const float*)d_in[8],  *bla = (const float*)d_in[9],  *Wra = (const float*)d_in[10];
    const float *Wa  = (const float*)d_in[11], *ba  = (const float*)d_in[12];
    const float *Wlm = (const float*)d_in[13], *blm = (const float*)d_in[14], *Wrm = (const float*)d_in[15];
    const float *Wm  = (const float*)d_in[16], *bm  = (const float*)d_in[17];
    float* out = (float*)d_out;

    float *h1, *h2, *rt, *mv;
    unsigned *xh, *xl, *aggh, *aggl, *h1h, *h1l, *h2h, *h2l;
    cudaGetSymbolAddress((void**)&h1,  g_h1);
    cudaGetSymbolAddress((void**)&h2,  g_h2);
    cudaGetSymbolAddress((void**)&rt,  g_rt);
    cudaGetSymbolAddress((void**)&mv,  g_mv);
    cudaGetSymbolAddress((void**)&xh,  g_xh);
    cudaGetSymbolAddress((void**)&xl,  g_xl);
    cudaGetSymbolAddress((void**)&aggh, g_aggh);
    cudaGetSymbolAddress((void**)&aggl, g_aggl);
    cudaGetSymbolAddress((void**)&h1h, g_h1h);
    cudaGetSymbolAddress((void**)&h1l, g_h1l);
    cudaGetSymbolAddress((void**)&h2h, g_h2h);
    cudaGetSymbolAddress((void**)&h2l, g_h2l);

    // operand pre-packing (independent of edges)
    k_cvt_w<<<(WTOT + 255) / 256, 256>>>(Wl1, Wr1, Wl2, Wr2, Wla, Wra, Wlm, Wrm);
    k_cvt_x<<<(NNODES * (FIN / 2) + 255) / 256, 256>>>(x);

    // CSR build
    k_detect<<<16, 256>>>((const long long*)ei);
    k_hist<<<(NEDGES + 255) / 256, 256>>>(ei);
    k_blockscan<<<SCAN_BLKS, 256>>>();
    k_scanbs<<<1, 256>>>();
    k_applyoff<<<SCAN_BLKS, 256>>>();
    k_scatter<<<(NEDGES + 255) / 256, 256>>>(ei);

    dim3 segGrid((NNODES * 32 + 255) / 256);
    dim3 gemmGrid(2, (NNODES + GBM - 1) / GBM);
    dim3 dualGrid(4, (NNODES + GBM - 1) / GBM);

    // layer 1
    k_segmax<FIN><<<segGrid, 256>>>(x, aggh, aggl);
    k_gemm_mma<<<gemmGrid, 256>>>(aggh, aggl, FIN, xh, xl, FIN,
                                  WOFF0, WOFF1, bl1, h1, h1h, h1l, NNODES);

    // layer 2
    k_segmax<HID><<<segGrid, 256>>>(h1, aggh, aggl);
    k_gemm_mma<<<gemmGrid, 256>>>(aggh, aggl, HID, h1h, h1l, HID,
                                  WOFF2, WOFF3, bl2, h2, h2h, h2l, NNODES);

    // layer 3 (shared segmax, dual-branch GEMM)
    k_segmax<HID><<<segGrid, 256>>>(h2, aggh, aggl);
    k_gemm_dual<<<dualGrid, 256>>>(aggh, aggl, h2h, h2l, bla, rt, blm, mv, NNODES);

    // heads
    k_heads<<<segGrid, 256>>>(Wa, ba, Wm, bm, out);
    (void)in_sizes; (void)n_in; (void)out_size;
}